// round 1
// baseline (speedup 1.0000x reference)
#include <cuda_runtime.h>
#include <math.h>

// Problem constants
static constexpr int NB = 16;           // B_Nq == B_Ns
static constexpr int NC = 512;          // C
static constexpr int NP = 1024;         // H*W
static constexpr long CP = (long)NC * NP;            // 524288
static constexpr long OUT_ALPHA = (long)NB * CP;     // 8388608
static constexpr long OUT_BETA  = OUT_ALPHA + (long)NB * NP;

// Scratch (device globals; allocation-free kernel_launch)
__device__ float g_fsmean[NC * NP];                // mean_b f_s  [C,P]   (2 MB)
__device__ float g_S[(long)NB * NC * NC];          // logits -> Ac [B,C,C] (16 MB)
__device__ float g_ksbar[NC];                      // w_sca_k[c]*mean_p fsmean
__device__ float g_rm_part[NB * 4 * NP];           // rowmean partials per M-tile
__device__ float g_qb_part[NB * 8 * NC];           // qsbar partials per N-tile
__device__ float g_beta[NB * NP];

// ---------------------------------------------------------------------------
// Stage 1: fs_mean[c,p] = mean over b of f_s[b,c,p]   (float4 vectorized)
// ---------------------------------------------------------------------------
__global__ __launch_bounds__(256) void k_fsmean(const float* __restrict__ fs) {
    const int i4 = blockIdx.x * 256 + threadIdx.x;   // 0..131071
    const float4* f4 = (const float4*)fs;
    float4 a = make_float4(0.f, 0.f, 0.f, 0.f);
#pragma unroll
    for (int b = 0; b < NB; b++) {
        float4 v = f4[(long)b * (CP / 4) + i4];
        a.x += v.x; a.y += v.y; a.z += v.z; a.w += v.w;
    }
    const float s = 1.0f / (float)NB;
    a.x *= s; a.y *= s; a.z *= s; a.w *= s;
    ((float4*)g_fsmean)[i4] = a;
}

// ---------------------------------------------------------------------------
// Stage 1b: ksbar[c] = w_sca_k[c] * mean_p fs_mean[c,p]
// ---------------------------------------------------------------------------
__global__ __launch_bounds__(256) void k_ksbar(const float* __restrict__ wsk) {
    const int c = blockIdx.x;
    const int t = threadIdx.x;
    const float* r = g_fsmean + (long)c * NP;
    float s = r[t] + r[t + 256] + r[t + 512] + r[t + 768];
    __shared__ float sh[8];
#pragma unroll
    for (int o = 16; o; o >>= 1) s += __shfl_xor_sync(0xffffffffu, s, o);
    if ((t & 31) == 0) sh[t >> 5] = s;
    __syncthreads();
    if (t == 0) {
        float tot = 0.f;
#pragma unroll
        for (int i = 0; i < 8; i++) tot += sh[i];
        g_ksbar[c] = wsk[c] * tot * (1.0f / (float)NP);
    }
}

// ---------------------------------------------------------------------------
// Stage 2: GEMM1 (NT): S_raw[b,c,d] = sum_p f_q[b,c,p] * fs_mean[d,p]
//   M=N=512, K=1024, batched over b. 128x128 tiles, 8x8 microtiles.
//   (per-channel weights + 1/P folded into the softmax stage)
// ---------------------------------------------------------------------------
__global__ __launch_bounds__(256) void k_gemm1(const float* __restrict__ fq) {
    __shared__ float As[8][128];
    __shared__ float Bt[8][128];
    const int b  = blockIdx.z;
    const int m0 = blockIdx.y * 128;
    const int n0 = blockIdx.x * 128;
    const float* A = fq + (long)b * CP;
    const int t  = threadIdx.x;
    const int tx = t & 15, ty = t >> 4;
    const int lr = t >> 1, lk = (t & 1) * 4;

    float acc[8][8] = {};
    for (int k0 = 0; k0 < NP; k0 += 8) {
        float4 a4 = *(const float4*)(A + (long)(m0 + lr) * NP + k0 + lk);
        float4 b4 = *(const float4*)(g_fsmean + (long)(n0 + lr) * NP + k0 + lk);
        As[lk + 0][lr] = a4.x; As[lk + 1][lr] = a4.y; As[lk + 2][lr] = a4.z; As[lk + 3][lr] = a4.w;
        Bt[lk + 0][lr] = b4.x; Bt[lk + 1][lr] = b4.y; Bt[lk + 2][lr] = b4.z; Bt[lk + 3][lr] = b4.w;
        __syncthreads();
#pragma unroll
        for (int k = 0; k < 8; k++) {
            float ar[8], br[8];
            *(float4*)(ar)     = *(const float4*)&As[k][ty * 8];
            *(float4*)(ar + 4) = *(const float4*)&As[k][ty * 8 + 4];
            *(float4*)(br)     = *(const float4*)&Bt[k][tx * 8];
            *(float4*)(br + 4) = *(const float4*)&Bt[k][tx * 8 + 4];
#pragma unroll
            for (int i = 0; i < 8; i++)
#pragma unroll
                for (int j = 0; j < 8; j++)
                    acc[i][j] = fmaf(ar[i], br[j], acc[i][j]);
        }
        __syncthreads();
    }
    float* Cb = g_S + (long)b * NC * NC;
#pragma unroll
    for (int i = 0; i < 8; i++) {
        const int c = m0 + ty * 8 + i;
        float* dst = Cb + (long)c * NC + n0 + tx * 8;
        *(float4*)dst       = make_float4(acc[i][0], acc[i][1], acc[i][2], acc[i][3]);
        *(float4*)(dst + 4) = make_float4(acc[i][4], acc[i][5], acc[i][6], acc[i][7]);
    }
}

// ---------------------------------------------------------------------------
// Stage 3: row softmax: Ac[b,c,:] = softmax(S_raw[b,c,d] * wq[c]*wk[d] / P)
//   one block per (b,c) row of 512; in-place in g_S.
// ---------------------------------------------------------------------------
__global__ __launch_bounds__(256) void k_softmax(const float* __restrict__ wq,
                                                 const float* __restrict__ wk) {
    const int row = blockIdx.x;
    const int b = row >> 9;
    const int c = row & (NC - 1);
    float* S = g_S + (long)(b * NC + c) * NC;
    const int t = threadIdx.x;
    const float sc = wq[c] * (1.0f / (float)NP);
    const float v0 = S[t]       * wk[t]       * sc;
    const float v1 = S[t + 256] * wk[t + 256] * sc;

    __shared__ float sh[33];
    float m = fmaxf(v0, v1);
#pragma unroll
    for (int o = 16; o; o >>= 1) m = fmaxf(m, __shfl_xor_sync(0xffffffffu, m, o));
    if ((t & 31) == 0) sh[t >> 5] = m;
    __syncthreads();
    if (t == 0) {
        float mm = sh[0];
#pragma unroll
        for (int i = 1; i < 8; i++) mm = fmaxf(mm, sh[i]);
        sh[32] = mm;
    }
    __syncthreads();
    m = sh[32];
    const float e0 = expf(v0 - m), e1 = expf(v1 - m);
    float s = e0 + e1;
#pragma unroll
    for (int o = 16; o; o >>= 1) s += __shfl_xor_sync(0xffffffffu, s, o);
    __syncthreads();
    if ((t & 31) == 0) sh[t >> 5] = s;
    __syncthreads();
    if (t == 0) {
        float ss = 0.f;
#pragma unroll
        for (int i = 0; i < 8; i++) ss += sh[i];
        sh[32] = ss;
    }
    __syncthreads();
    const float inv = 1.0f / sh[32];
    S[t]       = e0 * inv;
    S[t + 256] = e1 * inv;
}

// ---------------------------------------------------------------------------
// Stage 4: GEMM2 (NN): Fc[b,c,p] = sum_d Ac[b,c,d] * (wv[d]*fs_mean[d,p])
//   Fused epilogue:
//     out[b,c,p]   = f_q[b,c,p] + lam*Fc
//     rm_part      = sum_c_in_tile (Fc*wsq[c])*ksbar[c]      (for alpha)
//     qb_part      = sum_p_in_tile (Fc*wsq[c])               (for beta)
//   Deterministic: shared-memory tree reductions, no atomics.
// ---------------------------------------------------------------------------
__global__ __launch_bounds__(256) void k_gemm2(const float* __restrict__ fq,
                                               const float* __restrict__ wv,
                                               const float* __restrict__ wsq,
                                               const float* __restrict__ lamp,
                                               float* __restrict__ out) {
    __shared__ float smem[2048];
    float* As = smem;          // [8][128] k-major
    float* Bt = smem + 1024;   // [8][128]
    const int b  = blockIdx.z;
    const int m0 = blockIdx.y * 128;
    const int n0 = blockIdx.x * 128;
    const float* A = g_S + (long)b * NC * NC;
    const int t  = threadIdx.x;
    const int tx = t & 15, ty = t >> 4;
    const int lr = t >> 1, lk = (t & 1) * 4;
    const int kb = t >> 5, nb = (t & 31) * 4;

    float acc[8][8] = {};
    for (int k0 = 0; k0 < NC; k0 += 8) {
        float4 a4 = *(const float4*)(A + (long)(m0 + lr) * NC + k0 + lk);
        const float wvk = wv[k0 + kb];
        float4 f4 = *(const float4*)(g_fsmean + (long)(k0 + kb) * NP + n0 + nb);
        As[(lk + 0) * 128 + lr] = a4.x; As[(lk + 1) * 128 + lr] = a4.y;
        As[(lk + 2) * 128 + lr] = a4.z; As[(lk + 3) * 128 + lr] = a4.w;
        f4.x *= wvk; f4.y *= wvk; f4.z *= wvk; f4.w *= wvk;
        *(float4*)&Bt[kb * 128 + nb] = f4;
        __syncthreads();
#pragma unroll
        for (int k = 0; k < 8; k++) {
            float ar[8], br[8];
            *(float4*)(ar)     = *(const float4*)&As[k * 128 + ty * 8];
            *(float4*)(ar + 4) = *(const float4*)&As[k * 128 + ty * 8 + 4];
            *(float4*)(br)     = *(const float4*)&Bt[k * 128 + tx * 8];
            *(float4*)(br + 4) = *(const float4*)&Bt[k * 128 + tx * 8 + 4];
#pragma unroll
            for (int i = 0; i < 8; i++)
#pragma unroll
                for (int j = 0; j < 8; j++)
                    acc[i][j] = fmaf(ar[i], br[j], acc[i][j]);
        }
        __syncthreads();
    }

    // ---- fused epilogue ----
    const float lam = *lamp;
    float rm[8] = {};   // per-j (p) partial of sum_c qs*ksbar
    float qb[8] = {};   // per-i (c) partial of sum_p qs
#pragma unroll
    for (int i = 0; i < 8; i++) {
        const int c = m0 + ty * 8 + i;
        const float wc = wsq[c];
        const float kc = g_ksbar[c];
        const float* fr = fq + (long)b * CP + (long)c * NP + n0 + tx * 8;
        float* orow = out + (long)b * CP + (long)c * NP + n0 + tx * 8;
        const float4 f0 = *(const float4*)fr;
        const float4 f1 = *(const float4*)(fr + 4);
        float4 o0, o1;
        o0.x = fmaf(lam, acc[i][0], f0.x); o0.y = fmaf(lam, acc[i][1], f0.y);
        o0.z = fmaf(lam, acc[i][2], f0.z); o0.w = fmaf(lam, acc[i][3], f0.w);
        o1.x = fmaf(lam, acc[i][4], f1.x); o1.y = fmaf(lam, acc[i][5], f1.y);
        o1.z = fmaf(lam, acc[i][6], f1.z); o1.w = fmaf(lam, acc[i][7], f1.w);
        *(float4*)orow       = o0;
        *(float4*)(orow + 4) = o1;
#pragma unroll
        for (int j = 0; j < 8; j++) {
            const float qs = acc[i][j] * wc;
            rm[j] += qs * kc;
            qb[i] += qs;
        }
    }
    __syncthreads();
    // rowmean partial: reduce over ty (c direction) for each of 128 p columns
#pragma unroll
    for (int j = 0; j < 8; j++) smem[ty * 128 + tx * 8 + j] = rm[j];
    __syncthreads();
    if (t < 128) {
        float s = 0.f;
#pragma unroll
        for (int r = 0; r < 16; r++) s += smem[r * 128 + t];
        g_rm_part[(b * 4 + blockIdx.y) * NP + n0 + t] = s;
    }
    __syncthreads();
    // qsbar partial: reduce over tx (p direction) for each of 128 c rows
#pragma unroll
    for (int i = 0; i < 8; i++) smem[tx * 128 + ty * 8 + i] = qb[i];
    __syncthreads();
    if (t < 128) {
        float s = 0.f;
#pragma unroll
        for (int r = 0; r < 16; r++) s += smem[r * 128 + t];
        g_qb_part[(b * 8 + blockIdx.x) * NC + m0 + t] = s;
    }
}

// ---------------------------------------------------------------------------
// Stage 5: alpha[b,:] = softmax_p( rowmean[b,p] / (TAU*C) )
// ---------------------------------------------------------------------------
__global__ __launch_bounds__(256) void k_alpha(float* __restrict__ out_alpha) {
    const int b = blockIdx.x;
    const int t = threadIdx.x;
    float v[4];
#pragma unroll
    for (int u = 0; u < 4; u++) {
        const int p = t + u * 256;
        float s = 0.f;
#pragma unroll
        for (int mt = 0; mt < 4; mt++) s += g_rm_part[(b * 4 + mt) * NP + p];
        v[u] = s * (1.0f / 256.0f);  // 1/(TAU*C) = 1/(0.5*512)
    }
    __shared__ float sh[33];
    float m = fmaxf(fmaxf(v[0], v[1]), fmaxf(v[2], v[3]));
#pragma unroll
    for (int o = 16; o; o >>= 1) m = fmaxf(m, __shfl_xor_sync(0xffffffffu, m, o));
    if ((t & 31) == 0) sh[t >> 5] = m;
    __syncthreads();
    if (t == 0) {
        float mm = sh[0];
#pragma unroll
        for (int i = 1; i < 8; i++) mm = fmaxf(mm, sh[i]);
        sh[32] = mm;
    }
    __syncthreads();
    m = sh[32];
    float e[4];
    float s = 0.f;
#pragma unroll
    for (int u = 0; u < 4; u++) { e[u] = expf(v[u] - m); s += e[u]; }
#pragma unroll
    for (int o = 16; o; o >>= 1) s += __shfl_xor_sync(0xffffffffu, s, o);
    __syncthreads();
    if ((t & 31) == 0) sh[t >> 5] = s;
    __syncthreads();
    if (t == 0) {
        float ss = 0.f;
#pragma unroll
        for (int i = 0; i < 8; i++) ss += sh[i];
        sh[32] = ss;
    }
    __syncthreads();
    const float inv = 1.0f / sh[32];
#pragma unroll
    for (int u = 0; u < 4; u++) out_alpha[(long)b * NP + t + u * 256] = e[u] * inv;
}

// ---------------------------------------------------------------------------
// Stage 6: beta[b,:] = softmax_q( (1/(TAU*C)) * sum_c qsbar[b,c]*wsk[c]*fs_mean[c,q] )
// ---------------------------------------------------------------------------
__global__ __launch_bounds__(256) void k_beta(const float* __restrict__ wsk) {
    __shared__ float qsw[NC];
    __shared__ float sh[33];
    const int b = blockIdx.x;
    const int t = threadIdx.x;
    for (int c = t; c < NC; c += 256) {
        float s = 0.f;
#pragma unroll
        for (int nt = 0; nt < 8; nt++) s += g_qb_part[(b * 8 + nt) * NC + c];
        qsw[c] = s * (1.0f / (float)NP) * wsk[c];   // qsbar[b,c]*wsk[c]
    }
    __syncthreads();
    float acc[4] = {0.f, 0.f, 0.f, 0.f};
    for (int c = 0; c < NC; c++) {
        const float q = qsw[c];
        const float* fr = g_fsmean + (long)c * NP + t;
        acc[0] = fmaf(q, fr[0],   acc[0]);
        acc[1] = fmaf(q, fr[256], acc[1]);
        acc[2] = fmaf(q, fr[512], acc[2]);
        acc[3] = fmaf(q, fr[768], acc[3]);
    }
#pragma unroll
    for (int u = 0; u < 4; u++) acc[u] *= (1.0f / 256.0f);  // 1/(TAU*C)
    // softmax over 1024
    float m = fmaxf(fmaxf(acc[0], acc[1]), fmaxf(acc[2], acc[3]));
#pragma unroll
    for (int o = 16; o; o >>= 1) m = fmaxf(m, __shfl_xor_sync(0xffffffffu, m, o));
    if ((t & 31) == 0) sh[t >> 5] = m;
    __syncthreads();
    if (t == 0) {
        float mm = sh[0];
#pragma unroll
        for (int i = 1; i < 8; i++) mm = fmaxf(mm, sh[i]);
        sh[32] = mm;
    }
    __syncthreads();
    m = sh[32];
    float e[4];
    float s = 0.f;
#pragma unroll
    for (int u = 0; u < 4; u++) { e[u] = expf(acc[u] - m); s += e[u]; }
#pragma unroll
    for (int o = 16; o; o >>= 1) s += __shfl_xor_sync(0xffffffffu, s, o);
    __syncthreads();
    if ((t & 31) == 0) sh[t >> 5] = s;
    __syncthreads();
    if (t == 0) {
        float ss = 0.f;
#pragma unroll
        for (int i = 0; i < 8; i++) ss += sh[i];
        sh[32] = ss;
    }
    __syncthreads();
    const float inv = 1.0f / sh[32];
#pragma unroll
    for (int u = 0; u < 4; u++) g_beta[(long)b * NP + t + u * 256] = e[u] * inv;
}

// ---------------------------------------------------------------------------
// Stage 7: beta_mean broadcast: out_beta[s,q] = mean_b beta[b,q], s=0..15
// ---------------------------------------------------------------------------
__global__ __launch_bounds__(256) void k_betamean(float* __restrict__ out_beta) {
    const int q = blockIdx.x * 256 + threadIdx.x;  // 0..1023
    float s = 0.f;
#pragma unroll
    for (int b = 0; b < NB; b++) s += g_beta[(long)b * NP + q];
    s *= (1.0f / (float)NB);
#pragma unroll
    for (int r = 0; r < NB; r++) out_beta[(long)r * NP + q] = s;
}

// ---------------------------------------------------------------------------
extern "C" void kernel_launch(void* const* d_in, const int* in_sizes, int n_in,
                              void* d_out, int out_size) {
    const float* f_q     = (const float*)d_in[0];
    const float* f_s     = (const float*)d_in[1];
    const float* w_cca_q = (const float*)d_in[2];
    const float* w_cca_k = (const float*)d_in[3];
    const float* w_cca_v = (const float*)d_in[4];
    const float* w_sca_q = (const float*)d_in[5];
    const float* w_sca_k = (const float*)d_in[6];
    const float* lam     = (const float*)d_in[7];
    float* out = (float*)d_out;

    k_fsmean<<<512, 256>>>(f_s);
    k_ksbar<<<512, 256>>>(w_sca_k);
    k_gemm1<<<dim3(4, 4, NB), 256>>>(f_q);
    k_softmax<<<NB * NC, 256>>>(w_cca_q, w_cca_k);
    k_gemm2<<<dim3(8, 4, NB), 256>>>(f_q, w_cca_v, w_sca_q, lam, out);
    k_alpha<<<NB, 256>>>(out + OUT_ALPHA);
    k_beta<<<NB, 256>>>(w_sca_k);
    k_betamean<<<4, 256>>>(out + OUT_BETA);
}

// round 2
// speedup vs baseline: 2.2152x; 2.2152x over previous
#include <cuda_runtime.h>
#include <math.h>

// Problem constants
static constexpr int NB = 16;           // B_Nq == B_Ns
static constexpr int NC = 512;          // C
static constexpr int NP = 1024;         // H*W
static constexpr long CP = (long)NC * NP;            // 524288
static constexpr long OUT_ALPHA = (long)NB * CP;     // 8388608
static constexpr long OUT_BETA  = OUT_ALPHA + (long)NB * NP;

// Scratch (device globals; allocation-free kernel_launch)
__device__ float g_fsmean[NC * NP];                // mean_b f_s  [C,P]
__device__ float g_fsv[NC * NP];                   // w_cca_v[c]*fs_mean[c,p]
__device__ float g_S[(long)NB * NC * NC];          // logits -> Ac [B,C,C]
__device__ float g_ksbar[NC];                      // w_sca_k[c]*mean_p fsmean
__device__ float g_rm_part[NB * 4 * NP];           // rowmean partials per M-tile
__device__ float g_qb_part[NB * 8 * NC];           // qsbar partials per N-tile
__device__ float g_beta[NB * NP];

// ---------------------------------------------------------------------------
// PTX helpers
// ---------------------------------------------------------------------------
__device__ __forceinline__ unsigned f2tf(float f) {
    unsigned u;
    asm("cvt.rna.tf32.f32 %0, %1;" : "=r"(u) : "f"(f));
    return u;
}

__device__ __forceinline__ void mma_tf32(float c[4], const unsigned a[4], const unsigned b[2]) {
    asm volatile(
        "mma.sync.aligned.m16n8k8.row.col.f32.tf32.tf32.f32 "
        "{%0,%1,%2,%3}, {%4,%5,%6,%7}, {%8,%9}, {%0,%1,%2,%3};"
        : "+f"(c[0]), "+f"(c[1]), "+f"(c[2]), "+f"(c[3])
        : "r"(a[0]), "r"(a[1]), "r"(a[2]), "r"(a[3]), "r"(b[0]), "r"(b[1]));
}

__device__ __forceinline__ void cpa16(float* s, const float* g) {
    unsigned saddr = (unsigned)__cvta_generic_to_shared(s);
    asm volatile("cp.async.cg.shared.global [%0], [%1], 16;" :: "r"(saddr), "l"(g));
}
__device__ __forceinline__ void cpa_commit() { asm volatile("cp.async.commit_group;"); }
__device__ __forceinline__ void cpa_wait1()  { asm volatile("cp.async.wait_group 1;"); }
__device__ __forceinline__ void cpa_wait0()  { asm volatile("cp.async.wait_group 0;"); }

// ---------------------------------------------------------------------------
// Stage 1: fs_mean[c,p] = mean_b f_s ; fsv[c,p] = w_cca_v[c]*fs_mean[c,p]
// ---------------------------------------------------------------------------
__global__ __launch_bounds__(256) void k_fsmean(const float* __restrict__ fs,
                                                const float* __restrict__ wv) {
    const int i4 = blockIdx.x * 256 + threadIdx.x;   // 0..131071
    const float4* f4 = (const float4*)fs;
    float4 a = make_float4(0.f, 0.f, 0.f, 0.f);
#pragma unroll
    for (int b = 0; b < NB; b++) {
        float4 v = f4[(long)b * (CP / 4) + i4];
        a.x += v.x; a.y += v.y; a.z += v.z; a.w += v.w;
    }
    const float s = 1.0f / (float)NB;
    a.x *= s; a.y *= s; a.z *= s; a.w *= s;
    ((float4*)g_fsmean)[i4] = a;
    const int c = (i4 * 4) / NP;
    const float w = wv[c];
    float4 v = make_float4(a.x * w, a.y * w, a.z * w, a.w * w);
    ((float4*)g_fsv)[i4] = v;
}

// ---------------------------------------------------------------------------
// Stage 1b: ksbar[c] = w_sca_k[c] * mean_p fs_mean[c,p]
// ---------------------------------------------------------------------------
__global__ __launch_bounds__(256) void k_ksbar(const float* __restrict__ wsk) {
    const int c = blockIdx.x;
    const int t = threadIdx.x;
    const float* r = g_fsmean + (long)c * NP;
    float s = r[t] + r[t + 256] + r[t + 512] + r[t + 768];
    __shared__ float sh[8];
#pragma unroll
    for (int o = 16; o; o >>= 1) s += __shfl_xor_sync(0xffffffffu, s, o);
    if ((t & 31) == 0) sh[t >> 5] = s;
    __syncthreads();
    if (t == 0) {
        float tot = 0.f;
#pragma unroll
        for (int i = 0; i < 8; i++) tot += sh[i];
        g_ksbar[c] = wsk[c] * tot * (1.0f / (float)NP);
    }
}

// ---------------------------------------------------------------------------
// Stage 2: GEMM1 (NT) tf32 tensor-core:
//   S_raw[b,c,d] = sum_p f_q[b,c,p] * fs_mean[d,p]
//   M=N=512, K=1024. 128x128 CTA tiles, BK=32, cp.async double buffer.
// Shared layout: k-contig rows, stride 36 floats (bank-rotated, conflict-free)
// ---------------------------------------------------------------------------
static constexpr int AST = 36;                 // A/B shared row stride (floats)
static constexpr int G1_ABUF = 128 * AST;      // 4608 floats per buffer
static constexpr int G1_SMEM = 4 * G1_ABUF * 4; // bytes: As0,As1,Bs0,Bs1

__global__ __launch_bounds__(256, 2) void k_gemm1(const float* __restrict__ fq) {
    extern __shared__ float sm[];
    float* As = sm;                 // [2][128*36]
    float* Bs = sm + 2 * G1_ABUF;   // [2][128*36]
    const int b  = blockIdx.z;
    const int m0 = blockIdx.y * 128;
    const int n0 = blockIdx.x * 128;
    const float* A = fq + (long)b * CP;
    const float* B = g_fsmean;
    const int t = threadIdx.x;
    const int w = t >> 5, lane = t & 31;
    const int wm = w & 3, wn = w >> 2;      // 4 x 2 warp grid
    const int r = lane >> 2, q = lane & 3;
    const int lrow = t >> 3, lkv = (t & 7) * 4;   // loader mapping

    float acc[2][8][4] = {};

    auto load_stage = [&](int buf, int k0) {
        float* as = As + buf * G1_ABUF;
        float* bs = Bs + buf * G1_ABUF;
#pragma unroll
        for (int p = 0; p < 4; p++) {
            const int row = lrow + p * 32;
            cpa16(as + row * AST + lkv, A + (long)(m0 + row) * NP + k0 + lkv);
            cpa16(bs + row * AST + lkv, B + (long)(n0 + row) * NP + k0 + lkv);
        }
    };

    load_stage(0, 0);
    cpa_commit();

    const int NK = NP / 32;   // 32
    for (int ks = 0; ks < NK; ks++) {
        if (ks + 1 < NK) { load_stage((ks + 1) & 1, (ks + 1) * 32); cpa_commit(); cpa_wait1(); }
        else             { cpa_wait0(); }
        __syncthreads();
        const float* as = As + (ks & 1) * G1_ABUF;
        const float* bs = Bs + (ks & 1) * G1_ABUF;
#pragma unroll
        for (int kk = 0; kk < 4; kk++) {
            unsigned af[2][4];
#pragma unroll
            for (int mi = 0; mi < 2; mi++) {
                const float* base = as + (wm * 32 + mi * 16 + r) * AST + kk * 8 + q;
                af[mi][0] = f2tf(base[0]);
                af[mi][1] = f2tf(base[8 * AST]);
                af[mi][2] = f2tf(base[4]);
                af[mi][3] = f2tf(base[8 * AST + 4]);
            }
#pragma unroll
            for (int ni = 0; ni < 8; ni++) {
                const float* bb = bs + (wn * 64 + ni * 8 + r) * AST + kk * 8 + q;
                unsigned bf[2] = { f2tf(bb[0]), f2tf(bb[4]) };
                mma_tf32(acc[0][ni], af[0], bf);
                mma_tf32(acc[1][ni], af[1], bf);
            }
        }
        __syncthreads();
    }

    float* Cb = g_S + (long)b * NC * NC;
#pragma unroll
    for (int mi = 0; mi < 2; mi++)
#pragma unroll
    for (int ni = 0; ni < 8; ni++) {
        const int row = m0 + wm * 32 + mi * 16 + r;
        const int col = n0 + wn * 64 + ni * 8 + q * 2;
        float2 v0 = make_float2(acc[mi][ni][0], acc[mi][ni][1]);
        float2 v1 = make_float2(acc[mi][ni][2], acc[mi][ni][3]);
        *(float2*)&Cb[(long)row * NC + col]       = v0;
        *(float2*)&Cb[(long)(row + 8) * NC + col] = v1;
    }
}

// ---------------------------------------------------------------------------
// Stage 3: row softmax: Ac[b,c,:] = softmax(S_raw[b,c,d] * wq[c]*wk[d] / P)
// ---------------------------------------------------------------------------
__global__ __launch_bounds__(256) void k_softmax(const float* __restrict__ wq,
                                                 const float* __restrict__ wk) {
    const int row = blockIdx.x;
    const int b = row >> 9;
    const int c = row & (NC - 1);
    float* S = g_S + (long)(b * NC + c) * NC;
    const int t = threadIdx.x;
    const float sc = wq[c] * (1.0f / (float)NP);
    const float v0 = S[t]       * wk[t]       * sc;
    const float v1 = S[t + 256] * wk[t + 256] * sc;

    __shared__ float sh[33];
    float m = fmaxf(v0, v1);
#pragma unroll
    for (int o = 16; o; o >>= 1) m = fmaxf(m, __shfl_xor_sync(0xffffffffu, m, o));
    if ((t & 31) == 0) sh[t >> 5] = m;
    __syncthreads();
    if (t == 0) {
        float mm = sh[0];
#pragma unroll
        for (int i = 1; i < 8; i++) mm = fmaxf(mm, sh[i]);
        sh[32] = mm;
    }
    __syncthreads();
    m = sh[32];
    const float e0 = expf(v0 - m), e1 = expf(v1 - m);
    float s = e0 + e1;
#pragma unroll
    for (int o = 16; o; o >>= 1) s += __shfl_xor_sync(0xffffffffu, s, o);
    __syncthreads();
    if ((t & 31) == 0) sh[t >> 5] = s;
    __syncthreads();
    if (t == 0) {
        float ss = 0.f;
#pragma unroll
        for (int i = 0; i < 8; i++) ss += sh[i];
        sh[32] = ss;
    }
    __syncthreads();
    const float inv = 1.0f / sh[32];
    S[t]       = e0 * inv;
    S[t + 256] = e1 * inv;
}

// ---------------------------------------------------------------------------
// Stage 4: GEMM2 (NN) tf32 tensor-core:
//   Fc[b,c,p] = sum_d Ac[b,c,d] * fsv[d,p]     (fsv = wv[d]*fs_mean[d,p])
//   M=512(c), N=1024(p), K=512(d). 128x128 tiles, BK=32.
//   Fused epilogue: out = f_q + lam*Fc ; rowmean & qsbar partials
//   (deterministic shuffle + smem reductions, no atomics).
// Shared: A k-contig stride 36; B n-contig stride 136 (8k+n bank pattern).
// ---------------------------------------------------------------------------
static constexpr int BST = 136;
static constexpr int G2_ABUF = 128 * AST;      // 4608 floats
static constexpr int G2_BBUF = 32 * BST;       // 4352 floats
static constexpr int G2_SMEM = (2 * G2_ABUF + 2 * G2_BBUF) * 4;  // bytes

__global__ __launch_bounds__(256, 2) void k_gemm2(const float* __restrict__ fq,
                                                  const float* __restrict__ wsq,
                                                  const float* __restrict__ lamp,
                                                  float* __restrict__ out) {
    extern __shared__ float sm[];
    float* As = sm;                   // [2][128*36]
    float* Bs = sm + 2 * G2_ABUF;     // [2][32*136]
    const int b  = blockIdx.z;
    const int m0 = blockIdx.y * 128;
    const int n0 = blockIdx.x * 128;
    const float* A = g_S + (long)b * NC * NC;
    const int t = threadIdx.x;
    const int w = t >> 5, lane = t & 31;
    const int wm = w & 3, wn = w >> 2;
    const int r = lane >> 2, q = lane & 3;
    const int larow = t >> 3, lakv = (t & 7) * 4;      // A loader
    const int lbrow = t >> 5, lbnv = (t & 31) * 4;     // B loader

    float acc[2][8][4] = {};

    auto load_stage = [&](int buf, int k0) {
        float* as = As + buf * G2_ABUF;
        float* bs = Bs + buf * G2_BBUF;
#pragma unroll
        for (int p = 0; p < 4; p++) {
            const int row = larow + p * 32;
            cpa16(as + row * AST + lakv, A + (long)(m0 + row) * NC + k0 + lakv);
        }
#pragma unroll
        for (int p = 0; p < 4; p++) {
            const int row = lbrow + p * 8;
            cpa16(bs + row * BST + lbnv, g_fsv + (long)(k0 + row) * NP + n0 + lbnv);
        }
    };

    load_stage(0, 0);
    cpa_commit();

    const int NK = NC / 32;   // 16
    for (int ks = 0; ks < NK; ks++) {
        if (ks + 1 < NK) { load_stage((ks + 1) & 1, (ks + 1) * 32); cpa_commit(); cpa_wait1(); }
        else             { cpa_wait0(); }
        __syncthreads();
        const float* as = As + (ks & 1) * G2_ABUF;
        const float* bs = Bs + (ks & 1) * G2_BBUF;
#pragma unroll
        for (int kk = 0; kk < 4; kk++) {
            unsigned af[2][4];
#pragma unroll
            for (int mi = 0; mi < 2; mi++) {
                const float* base = as + (wm * 32 + mi * 16 + r) * AST + kk * 8 + q;
                af[mi][0] = f2tf(base[0]);
                af[mi][1] = f2tf(base[8 * AST]);
                af[mi][2] = f2tf(base[4]);
                af[mi][3] = f2tf(base[8 * AST + 4]);
            }
#pragma unroll
            for (int ni = 0; ni < 8; ni++) {
                const float* bb = bs + (kk * 8 + q) * BST + wn * 64 + ni * 8 + r;
                unsigned bf[2] = { f2tf(bb[0]), f2tf(bb[4 * BST]) };
                mma_tf32(acc[0][ni], af[0], bf);
                mma_tf32(acc[1][ni], af[1], bf);
            }
        }
        __syncthreads();
    }

    // ---- fused epilogue ----
    const float lam = *lamp;
    float rmloc[8][2] = {};
    float qbloc[2][2] = {};
#pragma unroll
    for (int mi = 0; mi < 2; mi++)
#pragma unroll
    for (int h = 0; h < 2; h++) {
        const int c = m0 + wm * 32 + mi * 16 + h * 8 + r;
        const float wc = wsq[c];
        const float wk = wc * g_ksbar[c];
        const float* fr = fq + (long)b * CP + (long)c * NP;
        float* orow = out + (long)b * CP + (long)c * NP;
        float qsum = 0.f;
#pragma unroll
        for (int ni = 0; ni < 8; ni++) {
            const int p = n0 + wn * 64 + ni * 8 + q * 2;
            const float v0 = acc[mi][ni][h * 2 + 0];
            const float v1 = acc[mi][ni][h * 2 + 1];
            const float2 f = *(const float2*)&fr[p];
            float2 o = make_float2(fmaf(lam, v0, f.x), fmaf(lam, v1, f.y));
            *(float2*)&orow[p] = o;
            rmloc[ni][0] += v0 * wk;
            rmloc[ni][1] += v1 * wk;
            qsum += v0 + v1;
        }
        qbloc[mi][h] = qsum * wc;
    }
    // rm: reduce over the 8 row-lanes (xor 4,8,16)
#pragma unroll
    for (int ni = 0; ni < 8; ni++)
#pragma unroll
    for (int j = 0; j < 2; j++) {
        float v = rmloc[ni][j];
        v += __shfl_xor_sync(0xffffffffu, v, 4);
        v += __shfl_xor_sync(0xffffffffu, v, 8);
        v += __shfl_xor_sync(0xffffffffu, v, 16);
        rmloc[ni][j] = v;
    }
    // qb: reduce over the 4 col-lanes (xor 1,2)
#pragma unroll
    for (int mi = 0; mi < 2; mi++)
#pragma unroll
    for (int h = 0; h < 2; h++) {
        float v = qbloc[mi][h];
        v += __shfl_xor_sync(0xffffffffu, v, 1);
        v += __shfl_xor_sync(0xffffffffu, v, 2);
        qbloc[mi][h] = v;
    }
    __syncthreads();
    float* rmstage = sm;            // [4][128]
    float* qbstage = sm + 512;      // [2][128]
    if (r == 0) {
#pragma unroll
        for (int ni = 0; ni < 8; ni++) {
            rmstage[wm * 128 + wn * 64 + ni * 8 + q * 2 + 0] = rmloc[ni][0];
            rmstage[wm * 128 + wn * 64 + ni * 8 + q * 2 + 1] = rmloc[ni][1];
        }
    }
    if (q == 0) {
#pragma unroll
        for (int mi = 0; mi < 2; mi++)
#pragma unroll
        for (int h = 0; h < 2; h++)
            qbstage[wn * 128 + wm * 32 + mi * 16 + h * 8 + r] = qbloc[mi][h];
    }
    __syncthreads();
    if (t < 128) {
        const float s = rmstage[t] + rmstage[128 + t] + rmstage[256 + t] + rmstage[384 + t];
        g_rm_part[(b * 4 + blockIdx.y) * NP + blockIdx.x * 128 + t] = s;
        const float s2 = qbstage[t] + qbstage[128 + t];
        g_qb_part[(b * 8 + blockIdx.x) * NC + blockIdx.y * 128 + t] = s2;
    }
}

// ---------------------------------------------------------------------------
// Stage 5: alpha[b,:] = softmax_p( rowmean[b,p] / (TAU*C) )
// ---------------------------------------------------------------------------
__global__ __launch_bounds__(256) void k_alpha(float* __restrict__ out_alpha) {
    const int b = blockIdx.x;
    const int t = threadIdx.x;
    float v[4];
#pragma unroll
    for (int u = 0; u < 4; u++) {
        const int p = t + u * 256;
        float s = 0.f;
#pragma unroll
        for (int mt = 0; mt < 4; mt++) s += g_rm_part[(b * 4 + mt) * NP + p];
        v[u] = s * (1.0f / 256.0f);
    }
    __shared__ float sh[33];
    float m = fmaxf(fmaxf(v[0], v[1]), fmaxf(v[2], v[3]));
#pragma unroll
    for (int o = 16; o; o >>= 1) m = fmaxf(m, __shfl_xor_sync(0xffffffffu, m, o));
    if ((t & 31) == 0) sh[t >> 5] = m;
    __syncthreads();
    if (t == 0) {
        float mm = sh[0];
#pragma unroll
        for (int i = 1; i < 8; i++) mm = fmaxf(mm, sh[i]);
        sh[32] = mm;
    }
    __syncthreads();
    m = sh[32];
    float e[4];
    float s = 0.f;
#pragma unroll
    for (int u = 0; u < 4; u++) { e[u] = expf(v[u] - m); s += e[u]; }
#pragma unroll
    for (int o = 16; o; o >>= 1) s += __shfl_xor_sync(0xffffffffu, s, o);
    __syncthreads();
    if ((t & 31) == 0) sh[t >> 5] = s;
    __syncthreads();
    if (t == 0) {
        float ss = 0.f;
#pragma unroll
        for (int i = 0; i < 8; i++) ss += sh[i];
        sh[32] = ss;
    }
    __syncthreads();
    const float inv = 1.0f / sh[32];
#pragma unroll
    for (int u = 0; u < 4; u++) out_alpha[(long)b * NP + t + u * 256] = e[u] * inv;
}

// ---------------------------------------------------------------------------
// Stage 6: beta[b,:] = softmax_q( (1/(TAU*C)) * sum_c qsbar[b,c]*wsk[c]*fs_mean[c,q] )
// ---------------------------------------------------------------------------
__global__ __launch_bounds__(256) void k_beta(const float* __restrict__ wsk) {
    __shared__ float qsw[NC];
    __shared__ float sh[33];
    const int b = blockIdx.x;
    const int t = threadIdx.x;
    for (int c = t; c < NC; c += 256) {
        float s = 0.f;
#pragma unroll
        for (int nt = 0; nt < 8; nt++) s += g_qb_part[(b * 8 + nt) * NC + c];
        qsw[c] = s * (1.0f / (float)NP) * wsk[c];
    }
    __syncthreads();
    float acc[4] = {0.f, 0.f, 0.f, 0.f};
    for (int c = 0; c < NC; c++) {
        const float qv = qsw[c];
        const float* fr = g_fsmean + (long)c * NP + t;
        acc[0] = fmaf(qv, fr[0],   acc[0]);
        acc[1] = fmaf(qv, fr[256], acc[1]);
        acc[2] = fmaf(qv, fr[512], acc[2]);
        acc[3] = fmaf(qv, fr[768], acc[3]);
    }
#pragma unroll
    for (int u = 0; u < 4; u++) acc[u] *= (1.0f / 256.0f);
    float m = fmaxf(fmaxf(acc[0], acc[1]), fmaxf(acc[2], acc[3]));
#pragma unroll
    for (int o = 16; o; o >>= 1) m = fmaxf(m, __shfl_xor_sync(0xffffffffu, m, o));
    if ((t & 31) == 0) sh[t >> 5] = m;
    __syncthreads();
    if (t == 0) {
        float mm = sh[0];
#pragma unroll
        for (int i = 1; i < 8; i++) mm = fmaxf(mm, sh[i]);
        sh[32] = mm;
    }
    __syncthreads();
    m = sh[32];
    float e[4];
    float s = 0.f;
#pragma unroll
    for (int u = 0; u < 4; u++) { e[u] = expf(acc[u] - m); s += e[u]; }
#pragma unroll
    for (int o = 16; o; o >>= 1) s += __shfl_xor_sync(0xffffffffu, s, o);
    __syncthreads();
    if ((t & 31) == 0) sh[t >> 5] = s;
    __syncthreads();
    if (t == 0) {
        float ss = 0.f;
#pragma unroll
        for (int i = 0; i < 8; i++) ss += sh[i];
        sh[32] = ss;
    }
    __syncthreads();
    const float inv = 1.0f / sh[32];
#pragma unroll
    for (int u = 0; u < 4; u++) g_beta[(long)b * NP + t + u * 256] = e[u] * inv;
}

// ---------------------------------------------------------------------------
// Stage 7: beta_mean broadcast
// ---------------------------------------------------------------------------
__global__ __launch_bounds__(256) void k_betamean(float* __restrict__ out_beta) {
    const int qi = blockIdx.x * 256 + threadIdx.x;
    float s = 0.f;
#pragma unroll
    for (int b = 0; b < NB; b++) s += g_beta[(long)b * NP + qi];
    s *= (1.0f / (float)NB);
#pragma unroll
    for (int rr = 0; rr < NB; rr++) out_beta[(long)rr * NP + qi] = s;
}

// ---------------------------------------------------------------------------
extern "C" void kernel_launch(void* const* d_in, const int* in_sizes, int n_in,
                              void* d_out, int out_size) {
    const float* f_q     = (const float*)d_in[0];
    const float* f_s     = (const float*)d_in[1];
    const float* w_cca_q = (const float*)d_in[2];
    const float* w_cca_k = (const float*)d_in[3];
    const float* w_cca_v = (const float*)d_in[4];
    const float* w_sca_q = (const float*)d_in[5];
    const float* w_sca_k = (const float*)d_in[6];
    const float* lam     = (const float*)d_in[7];
    float* out = (float*)d_out;

    cudaFuncSetAttribute(k_gemm1, cudaFuncAttributeMaxDynamicSharedMemorySize, G1_SMEM);
    cudaFuncSetAttribute(k_gemm2, cudaFuncAttributeMaxDynamicSharedMemorySize, G2_SMEM);

    k_fsmean<<<512, 256>>>(f_s, w_cca_v);
    k_ksbar<<<512, 256>>>(w_sca_k);
    k_gemm1<<<dim3(4, 4, NB), 256, G1_SMEM>>>(f_q);
    k_softmax<<<NB * NC, 256>>>(w_cca_q, w_cca_k);
    k_gemm2<<<dim3(8, 4, NB), 256, G2_SMEM>>>(f_q, w_sca_q, lam, out);
    k_alpha<<<NB, 256>>>(out + OUT_ALPHA);
    k_beta<<<NB, 256>>>(w_sca_k);
    k_betamean<<<4, 256>>>(out + OUT_BETA);
}

// round 3
// speedup vs baseline: 2.6388x; 1.1912x over previous
#include <cuda_runtime.h>
#include <cuda_bf16.h>
#include <math.h>

// Problem constants
static constexpr int NB = 16;           // B_Nq == B_Ns
static constexpr int NC = 512;          // C
static constexpr int NP = 1024;         // H*W
static constexpr long CP = (long)NC * NP;            // 524288
static constexpr long OUT_ALPHA = (long)NB * CP;     // 8388608
static constexpr long OUT_BETA  = OUT_ALPHA + (long)NB * NP;

// Scratch (device globals; allocation-free kernel_launch)
__device__ float          g_fsmean[NC * NP];          // mean_b f_s (fp32, for k_beta)
__device__ __nv_bfloat16  g_fsmean_h[NC * NP];        // bf16 copy (GEMM1 B)
__device__ __nv_bfloat16  g_fsv_h[NC * NP];           // bf16 w_cca_v[c]*fs_mean (GEMM2 B)
__device__ __nv_bfloat16  g_fq_h[(long)NB * CP];      // bf16 f_q (GEMM1 A)
__device__ float          g_S[(long)NB * NC * NC];    // GEMM1 logits (fp32)
__device__ __nv_bfloat16  g_Sh[(long)NB * NC * NC];   // softmaxed Ac (bf16, GEMM2 A)
__device__ float          g_ksbar[NC];
__device__ float          g_rm_part[NB * 4 * NP];
__device__ float          g_qb_part[NB * 8 * NC];
__device__ float          g_beta[NB * NP];

// ---------------------------------------------------------------------------
// PTX helpers
// ---------------------------------------------------------------------------
__device__ __forceinline__ unsigned sptr(const void* p) {
    return (unsigned)__cvta_generic_to_shared(p);
}
__device__ __forceinline__ void ldsm_x4(unsigned& r0, unsigned& r1, unsigned& r2, unsigned& r3,
                                        unsigned addr) {
    asm volatile("ldmatrix.sync.aligned.m8n8.x4.shared.b16 {%0,%1,%2,%3}, [%4];"
                 : "=r"(r0), "=r"(r1), "=r"(r2), "=r"(r3) : "r"(addr));
}
__device__ __forceinline__ void ldsm_x4_t(unsigned& r0, unsigned& r1, unsigned& r2, unsigned& r3,
                                          unsigned addr) {
    asm volatile("ldmatrix.sync.aligned.m8n8.x4.trans.shared.b16 {%0,%1,%2,%3}, [%4];"
                 : "=r"(r0), "=r"(r1), "=r"(r2), "=r"(r3) : "r"(addr));
}
__device__ __forceinline__ void mma_bf16(float c[4], const unsigned a[4], const unsigned b[2]) {
    asm volatile(
        "mma.sync.aligned.m16n8k16.row.col.f32.bf16.bf16.f32 "
        "{%0,%1,%2,%3}, {%4,%5,%6,%7}, {%8,%9}, {%0,%1,%2,%3};"
        : "+f"(c[0]), "+f"(c[1]), "+f"(c[2]), "+f"(c[3])
        : "r"(a[0]), "r"(a[1]), "r"(a[2]), "r"(a[3]), "r"(b[0]), "r"(b[1]));
}
__device__ __forceinline__ void cpa16(const void* s, const void* g) {
    unsigned saddr = sptr(s);
    asm volatile("cp.async.cg.shared.global [%0], [%1], 16;" :: "r"(saddr), "l"(g));
}
__device__ __forceinline__ void cpa_commit() { asm volatile("cp.async.commit_group;"); }
__device__ __forceinline__ void cpa_wait1()  { asm volatile("cp.async.wait_group 1;"); }
__device__ __forceinline__ void cpa_wait0()  { asm volatile("cp.async.wait_group 0;"); }

__device__ __forceinline__ unsigned pack_bf2(float lo, float hi) {
    __nv_bfloat162 h = __floats2bfloat162_rn(lo, hi);
    return *(unsigned*)&h;
}

// ---------------------------------------------------------------------------
// Stage 1 (prep): block == one channel row c.
//   fs_mean[c,:], bf16 copies, fsv_h = wv[c]*fs_mean (bf16), ksbar[c].
// ---------------------------------------------------------------------------
__global__ __launch_bounds__(256) void k_prep(const float* __restrict__ fs,
                                              const float* __restrict__ wv,
                                              const float* __restrict__ wsk) {
    const int c = blockIdx.x;
    const int t = threadIdx.x;
    const int i4 = c * 256 + t;   // float4 index; block covers row c exactly
    const float4* f4 = (const float4*)fs;
    float4 a = make_float4(0.f, 0.f, 0.f, 0.f);
#pragma unroll
    for (int b = 0; b < NB; b++) {
        float4 v = f4[(long)b * (CP / 4) + i4];
        a.x += v.x; a.y += v.y; a.z += v.z; a.w += v.w;
    }
    const float s = 1.0f / (float)NB;
    a.x *= s; a.y *= s; a.z *= s; a.w *= s;
    ((float4*)g_fsmean)[i4] = a;
    uint2 h = make_uint2(pack_bf2(a.x, a.y), pack_bf2(a.z, a.w));
    ((uint2*)g_fsmean_h)[i4] = h;
    const float w = wv[c];
    uint2 hv = make_uint2(pack_bf2(a.x * w, a.y * w), pack_bf2(a.z * w, a.w * w));
    ((uint2*)g_fsv_h)[i4] = hv;

    // ksbar: row sum
    float rs = a.x + a.y + a.z + a.w;
    __shared__ float sh[8];
#pragma unroll
    for (int o = 16; o; o >>= 1) rs += __shfl_xor_sync(0xffffffffu, rs, o);
    if ((t & 31) == 0) sh[t >> 5] = rs;
    __syncthreads();
    if (t == 0) {
        float tot = 0.f;
#pragma unroll
        for (int i = 0; i < 8; i++) tot += sh[i];
        g_ksbar[c] = wsk[c] * tot * (1.0f / (float)NP);
    }
}

// ---------------------------------------------------------------------------
// Stage 1b: f_q -> bf16
// ---------------------------------------------------------------------------
__global__ __launch_bounds__(256) void k_cvtq(const float* __restrict__ fq) {
    const long i4 = (long)blockIdx.x * 256 + threadIdx.x;  // 0..2097151
    float4 v = ((const float4*)fq)[i4];
    ((uint2*)g_fq_h)[i4] = make_uint2(pack_bf2(v.x, v.y), pack_bf2(v.z, v.w));
}

// ---------------------------------------------------------------------------
// Stage 2: GEMM1 (NT) bf16:  S[b,c,d] = sum_p fq_h[b,c,p] * fsmean_h[d,p]
//   128x128 tiles, BK=32, m16n8k16 + ldmatrix, cp.async double buffer.
//   Shared rows padded to 40 halves (80B) -> conflict-free ldmatrix.
// ---------------------------------------------------------------------------
static constexpr int BKH = 40;            // padded halves per k-contig row
static constexpr int T1H = 128 * BKH;     // halves per tile buffer

__global__ __launch_bounds__(256, 2) void k_gemm1() {
    __shared__ __nv_bfloat16 As[2][T1H];
    __shared__ __nv_bfloat16 Bs[2][T1H];
    const int b  = blockIdx.z;
    const int m0 = blockIdx.y * 128;
    const int n0 = blockIdx.x * 128;
    const __nv_bfloat16* A = g_fq_h + (long)b * CP;
    const __nv_bfloat16* B = g_fsmean_h;
    const int t = threadIdx.x;
    const int w = t >> 5, l = t & 31;
    const int wm = w & 3, wn = w >> 2;

    // loader mapping: 512 16B-chunks per tile; 2 per thread
    const int lrow0 = t >> 1;              // not used; use idx form below

    // ldmatrix lane offsets (bytes within buffer)
    unsigned aoff[2], boff[4];
#pragma unroll
    for (int mi = 0; mi < 2; mi++)
        aoff[mi] = ((wm * 32 + mi * 16 + (l & 15)) * BKH + (l >> 4) * 8) * 2;
#pragma unroll
    for (int g = 0; g < 4; g++)
        boff[g] = ((wn * 64 + g * 16 + ((l >> 4) << 3) + (l & 7)) * BKH + ((l >> 3) & 1) * 8) * 2;
    const unsigned asb = sptr(As), bsb = sptr(Bs);

    float acc[2][8][4] = {};

    auto load_stage = [&](int buf, int k0) {
        __nv_bfloat16* as = As[buf];
        __nv_bfloat16* bs = Bs[buf];
#pragma unroll
        for (int u = 0; u < 2; u++) {
            const int idx = u * 256 + t;
            const int row = idx >> 2, kc = (idx & 3) * 8;
            cpa16(as + row * BKH + kc, A + (long)(m0 + row) * NP + k0 + kc);
            cpa16(bs + row * BKH + kc, B + (long)(n0 + row) * NP + k0 + kc);
        }
    };

    load_stage(0, 0);
    cpa_commit();

    const int NK = NP / 32;   // 32
    for (int ks = 0; ks < NK; ks++) {
        if (ks + 1 < NK) { load_stage((ks + 1) & 1, (ks + 1) * 32); cpa_commit(); cpa_wait1(); }
        else             { cpa_wait0(); }
        __syncthreads();
        const unsigned ab = asb + (ks & 1) * (T1H * 2);
        const unsigned bb = bsb + (ks & 1) * (T1H * 2);
#pragma unroll
        for (int kk = 0; kk < 2; kk++) {
            unsigned af[2][4], bf[8][2];
#pragma unroll
            for (int mi = 0; mi < 2; mi++)
                ldsm_x4(af[mi][0], af[mi][1], af[mi][2], af[mi][3], ab + aoff[mi] + kk * 32);
#pragma unroll
            for (int g = 0; g < 4; g++)
                ldsm_x4(bf[2 * g][0], bf[2 * g][1], bf[2 * g + 1][0], bf[2 * g + 1][1],
                        bb + boff[g] + kk * 32);
#pragma unroll
            for (int mi = 0; mi < 2; mi++)
#pragma unroll
                for (int ni = 0; ni < 8; ni++)
                    mma_bf16(acc[mi][ni], af[mi], bf[ni]);
        }
        __syncthreads();
    }

    float* Cb = g_S + (long)b * NC * NC;
    const int r = l >> 2, q = l & 3;
#pragma unroll
    for (int mi = 0; mi < 2; mi++)
#pragma unroll
    for (int ni = 0; ni < 8; ni++) {
        const int row = m0 + wm * 32 + mi * 16 + r;
        const int col = n0 + wn * 64 + ni * 8 + q * 2;
        *(float2*)&Cb[(long)row * NC + col]       = make_float2(acc[mi][ni][0], acc[mi][ni][1]);
        *(float2*)&Cb[(long)(row + 8) * NC + col] = make_float2(acc[mi][ni][2], acc[mi][ni][3]);
    }
}

// ---------------------------------------------------------------------------
// Stage 3: warp-per-row softmax, fp32 in -> bf16 out
//   Ac[b,c,:] = softmax(S[b,c,d]*wq[c]*wk[d]/P)
// ---------------------------------------------------------------------------
__global__ __launch_bounds__(256) void k_softmax(const float* __restrict__ wq,
                                                 const float* __restrict__ wk) {
    const int row = blockIdx.x * 8 + (threadIdx.x >> 5);   // 0..8191
    const int l = threadIdx.x & 31;
    const int c = row & (NC - 1);
    const float* S = g_S + (long)row * NC;
    __nv_bfloat16* D = g_Sh + (long)row * NC;
    const float sc = wq[c] * (1.0f / (float)NP);
    float v[16];
#pragma unroll
    for (int u = 0; u < 16; u++) v[u] = S[l + 32 * u] * wk[l + 32 * u] * sc;
    float m = v[0];
#pragma unroll
    for (int u = 1; u < 16; u++) m = fmaxf(m, v[u]);
#pragma unroll
    for (int o = 16; o; o >>= 1) m = fmaxf(m, __shfl_xor_sync(0xffffffffu, m, o));
    float s = 0.f;
#pragma unroll
    for (int u = 0; u < 16; u++) { v[u] = __expf(v[u] - m); s += v[u]; }
#pragma unroll
    for (int o = 16; o; o >>= 1) s += __shfl_xor_sync(0xffffffffu, s, o);
    const float inv = 1.0f / s;
#pragma unroll
    for (int u = 0; u < 16; u++) D[l + 32 * u] = __float2bfloat16_rn(v[u] * inv);
}

// ---------------------------------------------------------------------------
// Stage 4: GEMM2 (NN) bf16: Fc[b,c,p] = sum_d Ac_h[b,c,d] * fsv_h[d,p]
//   A k-contig (like GEMM1), B n-contig (trans ldmatrix). Fused epilogue.
// ---------------------------------------------------------------------------
static constexpr int BNH = 136;           // padded halves per n-contig B row
static constexpr int T2A = 128 * BKH;     // A tile halves
static constexpr int T2B = 32 * BNH;      // B tile halves

__global__ __launch_bounds__(256, 2) void k_gemm2(const float* __restrict__ fq,
                                                  const float* __restrict__ wsq,
                                                  const float* __restrict__ lamp,
                                                  float* __restrict__ out) {
    __shared__ __nv_bfloat16 As[2][T2A];
    __shared__ __nv_bfloat16 Bs[2][T2B];
    const int b  = blockIdx.z;
    const int m0 = blockIdx.y * 128;
    const int n0 = blockIdx.x * 128;
    const __nv_bfloat16* A = g_Sh + (long)b * NC * NC;
    const int t = threadIdx.x;
    const int w = t >> 5, l = t & 31;
    const int wm = w & 3, wn = w >> 2;
    const int r = l >> 2, q = l & 3;

    unsigned aoff[2], boff[4];
#pragma unroll
    for (int mi = 0; mi < 2; mi++)
        aoff[mi] = ((wm * 32 + mi * 16 + (l & 15)) * BKH + (l >> 4) * 8) * 2;
#pragma unroll
    for (int g = 0; g < 4; g++)
        boff[g] = ((((l >> 3) & 1) * 8 + (l & 7)) * BNH + wn * 64 + g * 16 + (l >> 4) * 8) * 2;
    const unsigned asb = sptr(As), bsb = sptr(Bs);

    float acc[2][8][4] = {};

    auto load_stage = [&](int buf, int k0) {
        __nv_bfloat16* as = As[buf];
        __nv_bfloat16* bs = Bs[buf];
#pragma unroll
        for (int u = 0; u < 2; u++) {
            const int idx = u * 256 + t;
            const int arow = idx >> 2, akc = (idx & 3) * 8;
            cpa16(as + arow * BKH + akc, A + (long)(m0 + arow) * NC + k0 + akc);
            const int brow = idx >> 4, bnc = (idx & 15) * 8;
            cpa16(bs + brow * BNH + bnc, g_fsv_h + (long)(k0 + brow) * NP + n0 + bnc);
        }
    };

    load_stage(0, 0);
    cpa_commit();

    const int NK = NC / 32;   // 16
    for (int ks = 0; ks < NK; ks++) {
        if (ks + 1 < NK) { load_stage((ks + 1) & 1, (ks + 1) * 32); cpa_commit(); cpa_wait1(); }
        else             { cpa_wait0(); }
        __syncthreads();
        const unsigned ab = asb + (ks & 1) * (T2A * 2);
        const unsigned bb = bsb + (ks & 1) * (T2B * 2);
#pragma unroll
        for (int kk = 0; kk < 2; kk++) {
            unsigned af[2][4], bf[8][2];
#pragma unroll
            for (int mi = 0; mi < 2; mi++)
                ldsm_x4(af[mi][0], af[mi][1], af[mi][2], af[mi][3], ab + aoff[mi] + kk * 32);
#pragma unroll
            for (int g = 0; g < 4; g++)
                ldsm_x4_t(bf[2 * g][0], bf[2 * g][1], bf[2 * g + 1][0], bf[2 * g + 1][1],
                          bb + boff[g] + kk * 16 * BNH * 2);
#pragma unroll
            for (int mi = 0; mi < 2; mi++)
#pragma unroll
                for (int ni = 0; ni < 8; ni++)
                    mma_bf16(acc[mi][ni], af[mi], bf[ni]);
        }
        __syncthreads();
    }

    // ---- fused epilogue (identical fragment layout to round 2) ----
    const float lam = *lamp;
    float rmloc[8][2] = {};
    float qbloc[2][2] = {};
#pragma unroll
    for (int mi = 0; mi < 2; mi++)
#pragma unroll
    for (int h = 0; h < 2; h++) {
        const int c = m0 + wm * 32 + mi * 16 + h * 8 + r;
        const float wc = wsq[c];
        const float wk2 = wc * g_ksbar[c];
        const float* fr = fq + (long)b * CP + (long)c * NP;
        float* orow = out + (long)b * CP + (long)c * NP;
        float qsum = 0.f;
#pragma unroll
        for (int ni = 0; ni < 8; ni++) {
            const int p = n0 + wn * 64 + ni * 8 + q * 2;
            const float v0 = acc[mi][ni][h * 2 + 0];
            const float v1 = acc[mi][ni][h * 2 + 1];
            const float2 f = *(const float2*)&fr[p];
            *(float2*)&orow[p] = make_float2(fmaf(lam, v0, f.x), fmaf(lam, v1, f.y));
            rmloc[ni][0] += v0 * wk2;
            rmloc[ni][1] += v1 * wk2;
            qsum += v0 + v1;
        }
        qbloc[mi][h] = qsum * wc;
    }
#pragma unroll
    for (int ni = 0; ni < 8; ni++)
#pragma unroll
    for (int j = 0; j < 2; j++) {
        float v = rmloc[ni][j];
        v += __shfl_xor_sync(0xffffffffu, v, 4);
        v += __shfl_xor_sync(0xffffffffu, v, 8);
        v += __shfl_xor_sync(0xffffffffu, v, 16);
        rmloc[ni][j] = v;
    }
#pragma unroll
    for (int mi = 0; mi < 2; mi++)
#pragma unroll
    for (int h = 0; h < 2; h++) {
        float v = qbloc[mi][h];
        v += __shfl_xor_sync(0xffffffffu, v, 1);
        v += __shfl_xor_sync(0xffffffffu, v, 2);
        qbloc[mi][h] = v;
    }
    __syncthreads();
    float* stage = (float*)As;      // reuse smem
    float* rmstage = stage;         // [4][128]
    float* qbstage = stage + 512;   // [2][128]
    if (r == 0) {
#pragma unroll
        for (int ni = 0; ni < 8; ni++) {
            rmstage[wm * 128 + wn * 64 + ni * 8 + q * 2 + 0] = rmloc[ni][0];
            rmstage[wm * 128 + wn * 64 + ni * 8 + q * 2 + 1] = rmloc[ni][1];
        }
    }
    if (q == 0) {
#pragma unroll
        for (int mi = 0; mi < 2; mi++)
#pragma unroll
        for (int h = 0; h < 2; h++)
            qbstage[wn * 128 + wm * 32 + mi * 16 + h * 8 + r] = qbloc[mi][h];
    }
    __syncthreads();
    if (t < 128) {
        const float s = rmstage[t] + rmstage[128 + t] + rmstage[256 + t] + rmstage[384 + t];
        g_rm_part[(b * 4 + blockIdx.y) * NP + blockIdx.x * 128 + t] = s;
        const float s2 = qbstage[t] + qbstage[128 + t];
        g_qb_part[(b * 8 + blockIdx.x) * NC + blockIdx.y * 128 + t] = s2;
    }
}

// ---------------------------------------------------------------------------
// Stage 5: alpha[b,:] = softmax_p( rowmean[b,p] / (TAU*C) )
// ---------------------------------------------------------------------------
__global__ __launch_bounds__(256) void k_alpha(float* __restrict__ out_alpha) {
    const int b = blockIdx.x;
    const int t = threadIdx.x;
    float v[4];
#pragma unroll
    for (int u = 0; u < 4; u++) {
        const int p = t + u * 256;
        float s = 0.f;
#pragma unroll
        for (int mt = 0; mt < 4; mt++) s += g_rm_part[(b * 4 + mt) * NP + p];
        v[u] = s * (1.0f / 256.0f);
    }
    __shared__ float sh[33];
    float m = fmaxf(fmaxf(v[0], v[1]), fmaxf(v[2], v[3]));
#pragma unroll
    for (int o = 16; o; o >>= 1) m = fmaxf(m, __shfl_xor_sync(0xffffffffu, m, o));
    if ((t & 31) == 0) sh[t >> 5] = m;
    __syncthreads();
    if (t == 0) {
        float mm = sh[0];
#pragma unroll
        for (int i = 1; i < 8; i++) mm = fmaxf(mm, sh[i]);
        sh[32] = mm;
    }
    __syncthreads();
    m = sh[32];
    float s = 0.f;
#pragma unroll
    for (int u = 0; u < 4; u++) { v[u] = expf(v[u] - m); s += v[u]; }
#pragma unroll
    for (int o = 16; o; o >>= 1) s += __shfl_xor_sync(0xffffffffu, s, o);
    __syncthreads();
    if ((t & 31) == 0) sh[t >> 5] = s;
    __syncthreads();
    if (t == 0) {
        float ss = 0.f;
#pragma unroll
        for (int i = 0; i < 8; i++) ss += sh[i];
        sh[32] = ss;
    }
    __syncthreads();
    const float inv = 1.0f / sh[32];
#pragma unroll
    for (int u = 0; u < 4; u++) out_alpha[(long)b * NP + t + u * 256] = v[u] * inv;
}

// ---------------------------------------------------------------------------
// Stage 6: beta[b,:] = softmax_q( (1/(TAU*C)) * sum_c qsbar[b,c]*wsk[c]*fs_mean[c,q] )
// ---------------------------------------------------------------------------
__global__ __launch_bounds__(256) void k_beta(const float* __restrict__ wsk) {
    __shared__ float qsw[NC];
    __shared__ float sh[33];
    const int b = blockIdx.x;
    const int t = threadIdx.x;
    for (int c = t; c < NC; c += 256) {
        float s = 0.f;
#pragma unroll
        for (int nt = 0; nt < 8; nt++) s += g_qb_part[(b * 8 + nt) * NC + c];
        qsw[c] = s * (1.0f / (float)NP) * wsk[c];
    }
    __syncthreads();
    float acc[4] = {0.f, 0.f, 0.f, 0.f};
    for (int c = 0; c < NC; c++) {
        const float qv = qsw[c];
        const float* fr = g_fsmean + (long)c * NP + t;
        acc[0] = fmaf(qv, fr[0],   acc[0]);
        acc[1] = fmaf(qv, fr[256], acc[1]);
        acc[2] = fmaf(qv, fr[512], acc[2]);
        acc[3] = fmaf(qv, fr[768], acc[3]);
    }
#pragma unroll
    for (int u = 0; u < 4; u++) acc[u] *= (1.0f / 256.0f);
    float m = fmaxf(fmaxf(acc[0], acc[1]), fmaxf(acc[2], acc[3]));
#pragma unroll
    for (int o = 16; o; o >>= 1) m = fmaxf(m, __shfl_xor_sync(0xffffffffu, m, o));
    if ((t & 31) == 0) sh[t >> 5] = m;
    __syncthreads();
    if (t == 0) {
        float mm = sh[0];
#pragma unroll
        for (int i = 1; i < 8; i++) mm = fmaxf(mm, sh[i]);
        sh[32] = mm;
    }
    __syncthreads();
    m = sh[32];
    float s = 0.f;
#pragma unroll
    for (int u = 0; u < 4; u++) { acc[u] = expf(acc[u] - m); s += acc[u]; }
#pragma unroll
    for (int o = 16; o; o >>= 1) s += __shfl_xor_sync(0xffffffffu, s, o);
    __syncthreads();
    if ((t & 31) == 0) sh[t >> 5] = s;
    __syncthreads();
    if (t == 0) {
        float ss = 0.f;
#pragma unroll
        for (int i = 0; i < 8; i++) ss += sh[i];
        sh[32] = ss;
    }
    __syncthreads();
    const float inv = 1.0f / sh[32];
#pragma unroll
    for (int u = 0; u < 4; u++) g_beta[(long)b * NP + t + u * 256] = acc[u] * inv;
}

// ---------------------------------------------------------------------------
// Stage 7: beta_mean broadcast
// ---------------------------------------------------------------------------
__global__ __launch_bounds__(256) void k_betamean(float* __restrict__ out_beta) {
    const int qi = blockIdx.x * 256 + threadIdx.x;
    float s = 0.f;
#pragma unroll
    for (int b = 0; b < NB; b++) s += g_beta[(long)b * NP + qi];
    s *= (1.0f / (float)NB);
#pragma unroll
    for (int rr = 0; rr < NB; rr++) out_beta[(long)rr * NP + qi] = s;
}

// ---------------------------------------------------------------------------
extern "C" void kernel_launch(void* const* d_in, const int* in_sizes, int n_in,
                              void* d_out, int out_size) {
    const float* f_q     = (const float*)d_in[0];
    const float* f_s     = (const float*)d_in[1];
    const float* w_cca_q = (const float*)d_in[2];
    const float* w_cca_k = (const float*)d_in[3];
    const float* w_cca_v = (const float*)d_in[4];
    const float* w_sca_q = (const float*)d_in[5];
    const float* w_sca_k = (const float*)d_in[6];
    const float* lam     = (const float*)d_in[7];
    float* out = (float*)d_out;

    k_prep<<<512, 256>>>(f_s, w_cca_v, w_sca_k);
    k_cvtq<<<8192, 256>>>(f_q);
    k_gemm1<<<dim3(4, 4, NB), 256>>>();
    k_softmax<<<1024, 256>>>(w_cca_q, w_cca_k);
    k_gemm2<<<dim3(8, 4, NB), 256>>>(f_q, w_sca_q, lam, out);
    k_alpha<<<NB, 256>>>(out + OUT_ALPHA);
    k_beta<<<NB, 256>>>(w_sca_k);
    k_betamean<<<4, 256>>>(out + OUT_BETA);
}

// round 5
// speedup vs baseline: 2.6913x; 1.0199x over previous
#include <cuda_runtime.h>
#include <cuda_bf16.h>
#include <math.h>

// Problem constants
static constexpr int NB = 16;           // B_Nq == B_Ns
static constexpr int NC = 512;          // C
static constexpr int NP = 1024;         // H*W
static constexpr long CP = (long)NC * NP;            // 524288
static constexpr long OUT_ALPHA = (long)NB * CP;     // 8388608
static constexpr long OUT_BETA  = OUT_ALPHA + (long)NB * NP;

// Scratch (device globals; allocation-free kernel_launch)
__device__ float          g_fsmean[NC * NP];          // mean_b f_s (fp32)
__device__ __nv_bfloat16  g_fsmean_h[NC * NP];        // bf16 [d,p] (GEMM1 B)
__device__ __nv_bfloat16  g_fsvT[NP * NC];            // bf16 [p,d] = wv[d]*fsmean[d,p] (GEMM2 B)
__device__ __nv_bfloat16  g_fq_h[(long)NB * CP];      // bf16 f_q (GEMM1 A)
__device__ float          g_S[(long)NB * NC * NC];    // GEMM1 logits (fp32)
__device__ __nv_bfloat16  g_Sh[(long)NB * NC * NC];   // softmaxed Ac (bf16, GEMM2 A)
__device__ float          g_ksbar[NC];
__device__ float          g_rm_part[NB * 4 * NP];
__device__ float          g_qb_part[NB * 8 * NC];
__device__ float          g_beta[NB * NP];

// ---------------------------------------------------------------------------
// PTX helpers
// ---------------------------------------------------------------------------
__device__ __forceinline__ unsigned sptr(const void* p) {
    return (unsigned)__cvta_generic_to_shared(p);
}
__device__ __forceinline__ void ldsm_x4(unsigned& r0, unsigned& r1, unsigned& r2, unsigned& r3,
                                        unsigned addr) {
    asm volatile("ldmatrix.sync.aligned.m8n8.x4.shared.b16 {%0,%1,%2,%3}, [%4];"
                 : "=r"(r0), "=r"(r1), "=r"(r2), "=r"(r3) : "r"(addr));
}
__device__ __forceinline__ void mma_bf16(float c[4], const unsigned a[4], const unsigned b[2]) {
    asm volatile(
        "mma.sync.aligned.m16n8k16.row.col.f32.bf16.bf16.f32 "
        "{%0,%1,%2,%3}, {%4,%5,%6,%7}, {%8,%9}, {%0,%1,%2,%3};"
        : "+f"(c[0]), "+f"(c[1]), "+f"(c[2]), "+f"(c[3])
        : "r"(a[0]), "r"(a[1]), "r"(a[2]), "r"(a[3]), "r"(b[0]), "r"(b[1]));
}
__device__ __forceinline__ void cpa16(const void* s, const void* g) {
    unsigned saddr = sptr(s);
    asm volatile("cp.async.cg.shared.global [%0], [%1], 16;" :: "r"(saddr), "l"(g));
}
__device__ __forceinline__ void cpa_commit() { asm volatile("cp.async.commit_group;"); }
__device__ __forceinline__ void cpa_wait2()  { asm volatile("cp.async.wait_group 2;"); }
__device__ __forceinline__ void cpa_wait0()  { asm volatile("cp.async.wait_group 0;"); }

__device__ __forceinline__ unsigned pack_bf2(float lo, float hi) {
    __nv_bfloat162 h = __floats2bfloat162_rn(lo, hi);
    return *(unsigned*)&h;
}

// ---------------------------------------------------------------------------
// Stage 1 (prep): block == one channel row c. fs_mean, bf16 copy, ksbar.
// ---------------------------------------------------------------------------
__global__ __launch_bounds__(256) void k_prep(const float* __restrict__ fs,
                                              const float* __restrict__ wsk) {
    const int c = blockIdx.x;
    const int t = threadIdx.x;
    const int i4 = c * 256 + t;
    const float4* f4 = (const float4*)fs;
    float4 a = make_float4(0.f, 0.f, 0.f, 0.f);
#pragma unroll
    for (int b = 0; b < NB; b++) {
        float4 v = f4[(long)b * (CP / 4) + i4];
        a.x += v.x; a.y += v.y; a.z += v.z; a.w += v.w;
    }
    const float s = 1.0f / (float)NB;
    a.x *= s; a.y *= s; a.z *= s; a.w *= s;
    ((float4*)g_fsmean)[i4] = a;
    ((uint2*)g_fsmean_h)[i4] = make_uint2(pack_bf2(a.x, a.y), pack_bf2(a.z, a.w));

    float rs = a.x + a.y + a.z + a.w;
    __shared__ float sh[8];
#pragma unroll
    for (int o = 16; o; o >>= 1) rs += __shfl_xor_sync(0xffffffffu, rs, o);
    if ((t & 31) == 0) sh[t >> 5] = rs;
    __syncthreads();
    if (t == 0) {
        float tot = 0.f;
#pragma unroll
        for (int i = 0; i < 8; i++) tot += sh[i];
        g_ksbar[c] = wsk[c] * tot * (1.0f / (float)NP);
    }
}

// ---------------------------------------------------------------------------
// Stage 1b: f_q -> bf16
// ---------------------------------------------------------------------------
__global__ __launch_bounds__(256) void k_cvtq(const float* __restrict__ fq) {
    const long i4 = (long)blockIdx.x * 256 + threadIdx.x;
    float4 v = ((const float4*)fq)[i4];
    ((uint2*)g_fq_h)[i4] = make_uint2(pack_bf2(v.x, v.y), pack_bf2(v.z, v.w));
}

// ---------------------------------------------------------------------------
// Stage 1c: fsvT[p,d] = wv[d]*fsmean[d,p]  (bf16, K-major for GEMM2 B)
// ---------------------------------------------------------------------------
__global__ __launch_bounds__(256) void k_trans(const float* __restrict__ wv) {
    __shared__ float tile[32][33];
    const int p0 = blockIdx.x * 32, d0 = blockIdx.y * 32;
    const int tx = threadIdx.x & 31, ty = threadIdx.x >> 5;   // ty 0..7
#pragma unroll
    for (int r = 0; r < 4; r++) {
        const int d = d0 + ty + r * 8;
        tile[ty + r * 8][tx] = g_fsmean[(long)d * NP + p0 + tx] * wv[d];
    }
    __syncthreads();
#pragma unroll
    for (int r = 0; r < 4; r++) {
        const int p = p0 + ty + r * 8;
        g_fsvT[(long)p * NC + d0 + tx] = __float2bfloat16_rn(tile[tx][ty + r * 8]);
    }
}

// ---------------------------------------------------------------------------
// GEMM tiles: 128x128 CTA, BK=32, 4-stage cp.async, single sync per k-step.
// Shared rows padded to 40 halves (80B) -> conflict-free ldmatrix.
// ---------------------------------------------------------------------------
static constexpr int BKH = 40;               // padded halves per k-contig row
static constexpr int THALF = 128 * BKH;      // halves per (A or B) tile, one stage
static constexpr int STG = 4;
static constexpr int STG_H = 2 * THALF;      // halves per stage (A + B)
static constexpr int GEMM_SMEM = STG * STG_H * 2;   // 81920 bytes

// ---------------------------------------------------------------------------
// Stage 2: GEMM1 (NT) bf16: S[b,c,d] = sum_p fq_h[b,c,p] * fsmean_h[d,p]
// ---------------------------------------------------------------------------
__global__ __launch_bounds__(256, 2) void k_gemm1() {
    extern __shared__ __align__(16) __nv_bfloat16 smh[];
    const int b  = blockIdx.z;
    const int m0 = blockIdx.y * 128;
    const int n0 = blockIdx.x * 128;
    const __nv_bfloat16* A = g_fq_h + (long)b * CP;
    const __nv_bfloat16* B = g_fsmean_h;
    const int t = threadIdx.x;
    const int w = t >> 5, l = t & 31;
    const int wm = w & 3, wn = w >> 2;

    unsigned aoff[2], boff[4];
#pragma unroll
    for (int mi = 0; mi < 2; mi++)
        aoff[mi] = ((wm * 32 + mi * 16 + (l & 15)) * BKH + (l >> 4) * 8) * 2;
#pragma unroll
    for (int g = 0; g < 4; g++)
        boff[g] = ((wn * 64 + g * 16 + ((l >> 4) << 3) + (l & 7)) * BKH + ((l >> 3) & 1) * 8) * 2;
    const unsigned smb = sptr(smh);

    float acc[2][8][4] = {};

    auto load_stage = [&](int stg, int k0) {
        __nv_bfloat16* as = smh + stg * STG_H;
        __nv_bfloat16* bs = as + THALF;
#pragma unroll
        for (int u = 0; u < 2; u++) {
            const int idx = u * 256 + t;
            const int row = idx >> 2, kc = (idx & 3) * 8;
            cpa16(as + row * BKH + kc, A + (long)(m0 + row) * NP + k0 + kc);
            cpa16(bs + row * BKH + kc, B + (long)(n0 + row) * NP + k0 + kc);
        }
        cpa_commit();
    };

    const int NK = NP / 32;   // 32
    load_stage(0, 0);
    load_stage(1, 32);
    load_stage(2, 64);

    int stg = 0;
    for (int ks = 0; ks < NK; ks++) {
        cpa_wait2();
        __syncthreads();
        const unsigned ab = smb + stg * (STG_H * 2);
        const unsigned bb = ab + THALF * 2;
#pragma unroll
        for (int kk = 0; kk < 2; kk++) {
            unsigned af[2][4], bf[8][2];
#pragma unroll
            for (int mi = 0; mi < 2; mi++)
                ldsm_x4(af[mi][0], af[mi][1], af[mi][2], af[mi][3], ab + aoff[mi] + kk * 32);
#pragma unroll
            for (int g = 0; g < 4; g++)
                ldsm_x4(bf[2 * g][0], bf[2 * g][1], bf[2 * g + 1][0], bf[2 * g + 1][1],
                        bb + boff[g] + kk * 32);
#pragma unroll
            for (int mi = 0; mi < 2; mi++)
#pragma unroll
                for (int ni = 0; ni < 8; ni++)
                    mma_bf16(acc[mi][ni], af[mi], bf[ni]);
        }
        if (ks + 3 < NK) load_stage((ks + 3) & 3, (ks + 3) * 32);
        stg = (stg + 1) & 3;
    }
    cpa_wait0();

    float* Cb = g_S + (long)b * NC * NC;
    const int r = l >> 2, q = l & 3;
#pragma unroll
    for (int mi = 0; mi < 2; mi++)
#pragma unroll
    for (int ni = 0; ni < 8; ni++) {
        const int row = m0 + wm * 32 + mi * 16 + r;
        const int col = n0 + wn * 64 + ni * 8 + q * 2;
        *(float2*)&Cb[(long)row * NC + col]       = make_float2(acc[mi][ni][0], acc[mi][ni][1]);
        *(float2*)&Cb[(long)(row + 8) * NC + col] = make_float2(acc[mi][ni][2], acc[mi][ni][3]);
    }
}

// ---------------------------------------------------------------------------
// Stage 3: warp-per-row softmax, fp32 in -> bf16 out
// ---------------------------------------------------------------------------
__global__ __launch_bounds__(256) void k_softmax(const float* __restrict__ wq,
                                                 const float* __restrict__ wk) {
    const int row = blockIdx.x * 8 + (threadIdx.x >> 5);
    const int l = threadIdx.x & 31;
    const int c = row & (NC - 1);
    const float* S = g_S + (long)row * NC;
    __nv_bfloat16* D = g_Sh + (long)row * NC;
    const float sc = wq[c] * (1.0f / (float)NP);
    float v[16];
#pragma unroll
    for (int u = 0; u < 16; u++) v[u] = S[l + 32 * u] * wk[l + 32 * u] * sc;
    float m = v[0];
#pragma unroll
    for (int u = 1; u < 16; u++) m = fmaxf(m, v[u]);
#pragma unroll
    for (int o = 16; o; o >>= 1) m = fmaxf(m, __shfl_xor_sync(0xffffffffu, m, o));
    float s = 0.f;
#pragma unroll
    for (int u = 0; u < 16; u++) { v[u] = __expf(v[u] - m); s += v[u]; }
#pragma unroll
    for (int o = 16; o; o >>= 1) s += __shfl_xor_sync(0xffffffffu, s, o);
    const float inv = 1.0f / s;
#pragma unroll
    for (int u = 0; u < 16; u++) D[l + 32 * u] = __float2bfloat16_rn(v[u] * inv);
}

// ---------------------------------------------------------------------------
// Stage 4: GEMM2 (NT) bf16: Fc[b,c,p] = sum_d Ac_h[b,c,d] * fsvT[p,d]
//   Same NT tile code as GEMM1 (fsvT is K-major). Fused epilogue:
//   out = fq + lam*Fc ; rowmean & qsbar partials (deterministic).
// ---------------------------------------------------------------------------
__global__ __launch_bounds__(256, 2) void k_gemm2(const float* __restrict__ fq,
                                                  const float* __restrict__ wsq,
                                                  const float* __restrict__ lamp,
                                                  float* __restrict__ out) {
    extern __shared__ __align__(16) __nv_bfloat16 smh[];
    const int b  = blockIdx.z;
    const int m0 = blockIdx.y * 128;
    const int n0 = blockIdx.x * 128;
    const __nv_bfloat16* A = g_Sh + (long)b * NC * NC;
    const __nv_bfloat16* B = g_fsvT;
    const int t = threadIdx.x;
    const int w = t >> 5, l = t & 31;
    const int wm = w & 3, wn = w >> 2;
    const int r = l >> 2, q = l & 3;

    unsigned aoff[2], boff[4];
#pragma unroll
    for (int mi = 0; mi < 2; mi++)
        aoff[mi] = ((wm * 32 + mi * 16 + (l & 15)) * BKH + (l >> 4) * 8) * 2;
#pragma unroll
    for (int g = 0; g < 4; g++)
        boff[g] = ((wn * 64 + g * 16 + ((l >> 4) << 3) + (l & 7)) * BKH + ((l >> 3) & 1) * 8) * 2;
    const unsigned smb = sptr(smh);

    float acc[2][8][4] = {};

    auto load_stage = [&](int stg, int k0) {
        __nv_bfloat16* as = smh + stg * STG_H;
        __nv_bfloat16* bs = as + THALF;
#pragma unroll
        for (int u = 0; u < 2; u++) {
            const int idx = u * 256 + t;
            const int row = idx >> 2, kc = (idx & 3) * 8;
            cpa16(as + row * BKH + kc, A + (long)(m0 + row) * NC + k0 + kc);
            cpa16(bs + row * BKH + kc, B + (long)(n0 + row) * NC + k0 + kc);
        }
        cpa_commit();
    };

    const int NK = NC / 32;   // 16
    load_stage(0, 0);
    load_stage(1, 32);
    load_stage(2, 64);

    int stg = 0;
    for (int ks = 0; ks < NK; ks++) {
        cpa_wait2();
        __syncthreads();
        const unsigned ab = smb + stg * (STG_H * 2);
        const unsigned bb = ab + THALF * 2;
#pragma unroll
        for (int kk = 0; kk < 2; kk++) {
            unsigned af[2][4], bf[8][2];
#pragma unroll
            for (int mi = 0; mi < 2; mi++)
                ldsm_x4(af[mi][0], af[mi][1], af[mi][2], af[mi][3], ab + aoff[mi] + kk * 32);
#pragma unroll
            for (int g = 0; g < 4; g++)
                ldsm_x4(bf[2 * g][0], bf[2 * g][1], bf[2 * g + 1][0], bf[2 * g + 1][1],
                        bb + boff[g] + kk * 32);
#pragma unroll
            for (int mi = 0; mi < 2; mi++)
#pragma unroll
                for (int ni = 0; ni < 8; ni++)
                    mma_bf16(acc[mi][ni], af[mi], bf[ni]);
        }
        if (ks + 3 < NK) load_stage((ks + 3) & 3, (ks + 3) * 32);
        stg = (stg + 1) & 3;
    }
    cpa_wait0();

    // ---- fused epilogue ----
    const float lam = *lamp;
    float rmloc[8][2] = {};
    float qbloc[2][2] = {};
#pragma unroll
    for (int mi = 0; mi < 2; mi++)
#pragma unroll
    for (int h = 0; h < 2; h++) {
        const int c = m0 + wm * 32 + mi * 16 + h * 8 + r;
        const float wc = wsq[c];
        const float wk2 = wc * g_ksbar[c];
        const float* fr = fq + (long)b * CP + (long)c * NP;
        float* orow = out + (long)b * CP + (long)c * NP;
        float qsum = 0.f;
#pragma unroll
        for (int ni = 0; ni < 8; ni++) {
            const int p = n0 + wn * 64 + ni * 8 + q * 2;
            const float v0 = acc[mi][ni][h * 2 + 0];
            const float v1 = acc[mi][ni][h * 2 + 1];
            const float2 f = *(const float2*)&fr[p];
            *(float2*)&orow[p] = make_float2(fmaf(lam, v0, f.x), fmaf(lam, v1, f.y));
            rmloc[ni][0] += v0 * wk2;
            rmloc[ni][1] += v1 * wk2;
            qsum += v0 + v1;
        }
        qbloc[mi][h] = qsum * wc;
    }
#pragma unroll
    for (int ni = 0; ni < 8; ni++)
#pragma unroll
    for (int j = 0; j < 2; j++) {
        float v = rmloc[ni][j];
        v += __shfl_xor_sync(0xffffffffu, v, 4);
        v += __shfl_xor_sync(0xffffffffu, v, 8);
        v += __shfl_xor_sync(0xffffffffu, v, 16);
        rmloc[ni][j] = v;
    }
#pragma unroll
    for (int mi = 0; mi < 2; mi++)
#pragma unroll
    for (int h = 0; h < 2; h++) {
        float v = qbloc[mi][h];
        v += __shfl_xor_sync(0xffffffffu, v, 1);
        v += __shfl_xor_sync(0xffffffffu, v, 2);
        qbloc[mi][h] = v;
    }
    __syncthreads();
    float* stage = (float*)smh;      // reuse smem
    float* rmstage = stage;          // [4][128]
    float* qbstage = stage + 512;    // [2][128]
    if (r == 0) {
#pragma unroll
        for (int ni = 0; ni < 8; ni++) {
            rmstage[wm * 128 + wn * 64 + ni * 8 + q * 2 + 0] = rmloc[ni][0];
            rmstage[wm * 128 + wn * 64 + ni * 8 + q * 2 + 1] = rmloc[ni][1];
        }
    }
    if (q == 0) {
#pragma unroll
        for (int mi = 0; mi < 2; mi++)
#pragma unroll
        for (int h = 0; h < 2; h++)
            qbstage[wn * 128 + wm * 32 + mi * 16 + h * 8 + r] = qbloc[mi][h];
    }
    __syncthreads();
    if (t < 128) {
        const float s = rmstage[t] + rmstage[128 + t] + rmstage[256 + t] + rmstage[384 + t];
        g_rm_part[(b * 4 + blockIdx.y) * NP + blockIdx.x * 128 + t] = s;
        const float s2 = qbstage[t] + qbstage[128 + t];
        g_qb_part[(b * 8 + blockIdx.x) * NC + blockIdx.y * 128 + t] = s2;
    }
}

// ---------------------------------------------------------------------------
// Stage 5: alpha[b,:] = softmax_p( rowmean[b,p] / (TAU*C) )
// ---------------------------------------------------------------------------
__global__ __launch_bounds__(256) void k_alpha(float* __restrict__ out_alpha) {
    const int b = blockIdx.x;
    const int t = threadIdx.x;
    float v[4];
#pragma unroll
    for (int u = 0; u < 4; u++) {
        const int p = t + u * 256;
        float s = 0.f;
#pragma unroll
        for (int mt = 0; mt < 4; mt++) s += g_rm_part[(b * 4 + mt) * NP + p];
        v[u] = s * (1.0f / 256.0f);
    }
    __shared__ float sh[33];
    float m = fmaxf(fmaxf(v[0], v[1]), fmaxf(v[2], v[3]));
#pragma unroll
    for (int o = 16; o; o >>= 1) m = fmaxf(m, __shfl_xor_sync(0xffffffffu, m, o));
    if ((t & 31) == 0) sh[t >> 5] = m;
    __syncthreads();
    if (t == 0) {
        float mm = sh[0];
#pragma unroll
        for (int i = 1; i < 8; i++) mm = fmaxf(mm, sh[i]);
        sh[32] = mm;
    }
    __syncthreads();
    m = sh[32];
    float s = 0.f;
#pragma unroll
    for (int u = 0; u < 4; u++) { v[u] = expf(v[u] - m); s += v[u]; }
#pragma unroll
    for (int o = 16; o; o >>= 1) s += __shfl_xor_sync(0xffffffffu, s, o);
    __syncthreads();
    if ((t & 31) == 0) sh[t >> 5] = s;
    __syncthreads();
    if (t == 0) {
        float ss = 0.f;
#pragma unroll
        for (int i = 0; i < 8; i++) ss += sh[i];
        sh[32] = ss;
    }
    __syncthreads();
    const float inv = 1.0f / sh[32];
#pragma unroll
    for (int u = 0; u < 4; u++) out_alpha[(long)b * NP + t + u * 256] = v[u] * inv;
}

// ---------------------------------------------------------------------------
// Stage 6: beta
// ---------------------------------------------------------------------------
__global__ __launch_bounds__(256) void k_beta(const float* __restrict__ wsk) {
    __shared__ float qsw[NC];
    __shared__ float sh[33];
    const int b = blockIdx.x;
    const int t = threadIdx.x;
    for (int c = t; c < NC; c += 256) {
        float s = 0.f;
#pragma unroll
        for (int nt = 0; nt < 8; nt++) s += g_qb_part[(b * 8 + nt) * NC + c];
        qsw[c] = s * (1.0f / (float)NP) * wsk[c];
    }
    __syncthreads();
    float acc[4] = {0.f, 0.f, 0.f, 0.f};
    for (int c = 0; c < NC; c++) {
        const float qv = qsw[c];
        const float* fr = g_fsmean + (long)c * NP + t;
        acc[0] = fmaf(qv, fr[0],   acc[0]);
        acc[1] = fmaf(qv, fr[256], acc[1]);
        acc[2] = fmaf(qv, fr[512], acc[2]);
        acc[3] = fmaf(qv, fr[768], acc[3]);
    }
#pragma unroll
    for (int u = 0; u < 4; u++) acc[u] *= (1.0f / 256.0f);
    float m = fmaxf(fmaxf(acc[0], acc[1]), fmaxf(acc[2], acc[3]));
#pragma unroll
    for (int o = 16; o; o >>= 1) m = fmaxf(m, __shfl_xor_sync(0xffffffffu, m, o));
    if ((t & 31) == 0) sh[t >> 5] = m;
    __syncthreads();
    if (t == 0) {
        float mm = sh[0];
#pragma unroll
        for (int i = 1; i < 8; i++) mm = fmaxf(mm, sh[i]);
        sh[32] = mm;
    }
    __syncthreads();
    m = sh[32];
    float s = 0.f;
#pragma unroll
    for (int u = 0; u < 4; u++) { acc[u] = expf(acc[u] - m); s += acc[u]; }
#pragma unroll
    for (int o = 16; o; o >>= 1) s += __shfl_xor_sync(0xffffffffu, s, o);
    __syncthreads();
    if ((t & 31) == 0) sh[t >> 5] = s;
    __syncthreads();
    if (t == 0) {
        float ss = 0.f;
#pragma unroll
        for (int i = 0; i < 8; i++) ss += sh[i];
        sh[32] = ss;
    }
    __syncthreads();
    const float inv = 1.0f / sh[32];
#pragma unroll
    for (int u = 0; u < 4; u++) g_beta[(long)b * NP + t + u * 256] = acc[u] * inv;
}

// ---------------------------------------------------------------------------
// Stage 7: beta_mean broadcast
// ---------------------------------------------------------------------------
__global__ __launch_bounds__(256) void k_betamean(float* __restrict__ out_beta) {
    const int qi = blockIdx.x * 256 + threadIdx.x;
    float s = 0.f;
#pragma unroll
    for (int b = 0; b < NB; b++) s += g_beta[(long)b * NP + qi];
    s *= (1.0f / (float)NB);
#pragma unroll
    for (int rr = 0; rr < NB; rr++) out_beta[(long)rr * NP + qi] = s;
}

// ---------------------------------------------------------------------------
extern "C" void kernel_launch(void* const* d_in, const int* in_sizes, int n_in,
                              void* d_out, int out_size) {
    const float* f_q     = (const float*)d_in[0];
    const float* f_s     = (const float*)d_in[1];
    const float* w_cca_q = (const float*)d_in[2];
    const float* w_cca_k = (const float*)d_in[3];
    const float* w_cca_v = (const float*)d_in[4];
    const float* w_sca_q = (const float*)d_in[5];
    const float* w_sca_k = (const float*)d_in[6];
    const float* lam     = (const float*)d_in[7];
    float* out = (float*)d_out;

    cudaFuncSetAttribute(k_gemm1, cudaFuncAttributeMaxDynamicSharedMemorySize, GEMM_SMEM);
    cudaFuncSetAttribute(k_gemm2, cudaFuncAttributeMaxDynamicSharedMemorySize, GEMM_SMEM);

    k_prep<<<512, 256>>>(f_s, w_sca_k);
    k_trans<<<dim3(32, 16), 256>>>(w_cca_v);
    k_cvtq<<<8192, 256>>>(f_q);
    k_gemm1<<<dim3(4, 4, NB), 256, GEMM_SMEM>>>();
    k_softmax<<<1024, 256>>>(w_cca_q, w_cca_k);
    k_gemm2<<<dim3(8, 4, NB), 256, GEMM_SMEM>>>(f_q, w_sca_q, lam, out);
    k_alpha<<<NB, 256>>>(out + OUT_ALPHA);
    k_beta<<<NB, 256>>>(w_sca_k);
    k_betamean<<<4, 256>>>(out + OUT_BETA);
}

// round 6
// speedup vs baseline: 3.8298x; 1.4230x over previous
#include <cuda_runtime.h>
#include <cuda_bf16.h>
#include <math.h>

// Problem constants
static constexpr int NB = 16;           // B_Nq == B_Ns
static constexpr int NC = 512;          // C
static constexpr int NP = 1024;         // H*W
static constexpr long CP = (long)NC * NP;            // 524288
static constexpr long OUT_ALPHA = (long)NB * CP;     // 8388608
static constexpr long OUT_BETA  = OUT_ALPHA + (long)NB * NP;

// Scratch (device globals; allocation-free kernel_launch)
__device__ float          g_fsmean[NC * NP];          // mean_b f_s (fp32)
__device__ __nv_bfloat16  g_fsmean_h[NC * NP];        // bf16 [d,p] (GEMM1 B)
__device__ __nv_bfloat16  g_fsvT[NP * NC];            // bf16 [p,d] = wv[d]*fsmean[d,p]
__device__ __nv_bfloat16  g_fq_h[(long)NB * CP];      // bf16 f_q (GEMM1 A)
__device__ float          g_S[(long)NB * NC * NC];    // GEMM1 logits (fp32)
__device__ __nv_bfloat16  g_Sh[(long)NB * NC * NC];   // softmaxed Ac (bf16)
__device__ float          g_ksbar[NC];
__device__ float          g_rm_part[NB * 4 * NP];
__device__ float          g_qb_part[NB * 8 * NC];
__device__ float          g_beta[NB * NP];            // beta logits -> beta

// ---------------------------------------------------------------------------
// PTX helpers
// ---------------------------------------------------------------------------
__device__ __forceinline__ unsigned sptr(const void* p) {
    return (unsigned)__cvta_generic_to_shared(p);
}
__device__ __forceinline__ void ldsm_x4(unsigned& r0, unsigned& r1, unsigned& r2, unsigned& r3,
                                        unsigned addr) {
    asm volatile("ldmatrix.sync.aligned.m8n8.x4.shared.b16 {%0,%1,%2,%3}, [%4];"
                 : "=r"(r0), "=r"(r1), "=r"(r2), "=r"(r3) : "r"(addr));
}
__device__ __forceinline__ void mma_bf16(float c[4], const unsigned a[4], const unsigned b[2]) {
    asm volatile(
        "mma.sync.aligned.m16n8k16.row.col.f32.bf16.bf16.f32 "
        "{%0,%1,%2,%3}, {%4,%5,%6,%7}, {%8,%9}, {%0,%1,%2,%3};"
        : "+f"(c[0]), "+f"(c[1]), "+f"(c[2]), "+f"(c[3])
        : "r"(a[0]), "r"(a[1]), "r"(a[2]), "r"(a[3]), "r"(b[0]), "r"(b[1]));
}
__device__ __forceinline__ void cpa16(const void* s, const void* g) {
    unsigned saddr = sptr(s);
    asm volatile("cp.async.cg.shared.global [%0], [%1], 16;" :: "r"(saddr), "l"(g));
}
__device__ __forceinline__ void cpa_commit() { asm volatile("cp.async.commit_group;"); }
__device__ __forceinline__ void cpa_wait1()  { asm volatile("cp.async.wait_group 1;"); }
__device__ __forceinline__ void cpa_wait0()  { asm volatile("cp.async.wait_group 0;"); }

__device__ __forceinline__ unsigned pack_bf2(float lo, float hi) {
    __nv_bfloat162 h = __floats2bfloat162_rn(lo, hi);
    return *(unsigned*)&h;
}

// ---------------------------------------------------------------------------
// Stage 1 (prep): block == one channel row c. fs_mean, bf16 copy, ksbar.
// ---------------------------------------------------------------------------
__global__ __launch_bounds__(256) void k_prep(const float* __restrict__ fs,
                                              const float* __restrict__ wsk) {
    const int c = blockIdx.x;
    const int t = threadIdx.x;
    const int i4 = c * 256 + t;
    const float4* f4 = (const float4*)fs;
    float4 a = make_float4(0.f, 0.f, 0.f, 0.f);
#pragma unroll
    for (int b = 0; b < NB; b++) {
        float4 v = f4[(long)b * (CP / 4) + i4];
        a.x += v.x; a.y += v.y; a.z += v.z; a.w += v.w;
    }
    const float s = 1.0f / (float)NB;
    a.x *= s; a.y *= s; a.z *= s; a.w *= s;
    ((float4*)g_fsmean)[i4] = a;
    ((uint2*)g_fsmean_h)[i4] = make_uint2(pack_bf2(a.x, a.y), pack_bf2(a.z, a.w));

    float rs = a.x + a.y + a.z + a.w;
    __shared__ float sh[8];
#pragma unroll
    for (int o = 16; o; o >>= 1) rs += __shfl_xor_sync(0xffffffffu, rs, o);
    if ((t & 31) == 0) sh[t >> 5] = rs;
    __syncthreads();
    if (t == 0) {
        float tot = 0.f;
#pragma unroll
        for (int i = 0; i < 8; i++) tot += sh[i];
        g_ksbar[c] = wsk[c] * tot * (1.0f / (float)NP);
    }
}

// ---------------------------------------------------------------------------
// Stage 1b: f_q -> bf16
// ---------------------------------------------------------------------------
__global__ __launch_bounds__(256) void k_cvtq(const float* __restrict__ fq) {
    const long i4 = (long)blockIdx.x * 256 + threadIdx.x;
    float4 v = ((const float4*)fq)[i4];
    ((uint2*)g_fq_h)[i4] = make_uint2(pack_bf2(v.x, v.y), pack_bf2(v.z, v.w));
}

// ---------------------------------------------------------------------------
// Stage 1c: fsvT[p,d] = wv[d]*fsmean[d,p]  (bf16, K-major for GEMM2 B)
// ---------------------------------------------------------------------------
__global__ __launch_bounds__(256) void k_trans(const float* __restrict__ wv) {
    __shared__ float tile[32][33];
    const int p0 = blockIdx.x * 32, d0 = blockIdx.y * 32;
    const int tx = threadIdx.x & 31, ty = threadIdx.x >> 5;   // ty 0..7
#pragma unroll
    for (int r = 0; r < 4; r++) {
        const int d = d0 + ty + r * 8;
        tile[ty + r * 8][tx] = g_fsmean[(long)d * NP + p0 + tx] * wv[d];
    }
    __syncthreads();
#pragma unroll
    for (int r = 0; r < 4; r++) {
        const int p = p0 + ty + r * 8;
        g_fsvT[(long)p * NC + d0 + tx] = __float2bfloat16_rn(tile[tx][ty + r * 8]);
    }
}

// ---------------------------------------------------------------------------
// GEMM tiles: 128x128 CTA, BK=64, 3-stage cp.async, single sync per k-step.
// Shared rows padded to 72 halves (144B) -> conflict-free ldmatrix.
// ---------------------------------------------------------------------------
static constexpr int BKH = 72;               // padded halves per k-contig row
static constexpr int THALF = 128 * BKH;      // halves per (A or B) tile, one stage
static constexpr int STG = 3;
static constexpr int STG_H = 2 * THALF;      // halves per stage (A + B)
static constexpr int GEMM_SMEM = STG * STG_H * 2;   // 110592 bytes

// ---------------------------------------------------------------------------
// Stage 2: GEMM1 (NT) bf16: S[b,c,d] = sum_p fq_h[b,c,p] * fsmean_h[d,p]
// ---------------------------------------------------------------------------
__global__ __launch_bounds__(256, 2) void k_gemm1() {
    extern __shared__ __align__(16) __nv_bfloat16 smh[];
    const int b  = blockIdx.z;
    const int m0 = blockIdx.y * 128;
    const int n0 = blockIdx.x * 128;
    const __nv_bfloat16* A = g_fq_h + (long)b * CP;
    const __nv_bfloat16* B = g_fsmean_h;
    const int t = threadIdx.x;
    const int w = t >> 5, l = t & 31;
    const int wm = w & 3, wn = w >> 2;

    unsigned aoff[2], boff[4];
#pragma unroll
    for (int mi = 0; mi < 2; mi++)
        aoff[mi] = ((wm * 32 + mi * 16 + (l & 15)) * BKH + (l >> 4) * 8) * 2;
#pragma unroll
    for (int g = 0; g < 4; g++)
        boff[g] = ((wn * 64 + g * 16 + ((l >> 4) << 3) + (l & 7)) * BKH + ((l >> 3) & 1) * 8) * 2;
    const unsigned smb = sptr(smh);

    float acc[2][8][4] = {};

    auto load_stage = [&](int stg, int k0) {
        __nv_bfloat16* as = smh + stg * STG_H;
        __nv_bfloat16* bs = as + THALF;
#pragma unroll
        for (int u = 0; u < 4; u++) {
            const int idx = u * 256 + t;             // 0..1023
            const int row = idx >> 3, kc = (idx & 7) * 8;
            cpa16(as + row * BKH + kc, A + (long)(m0 + row) * NP + k0 + kc);
            cpa16(bs + row * BKH + kc, B + (long)(n0 + row) * NP + k0 + kc);
        }
        cpa_commit();
    };

    const int NK = NP / 64;   // 16
    load_stage(0, 0);
    load_stage(1, 64);

    int stg = 0;
    for (int ks = 0; ks < NK; ks++) {
        if (ks + 1 < NK) cpa_wait1(); else cpa_wait0();
        __syncthreads();
        const unsigned ab = smb + stg * (STG_H * 2);
        const unsigned bb = ab + THALF * 2;
#pragma unroll
        for (int kk = 0; kk < 4; kk++) {
            unsigned af[2][4], bf[8][2];
#pragma unroll
            for (int mi = 0; mi < 2; mi++)
                ldsm_x4(af[mi][0], af[mi][1], af[mi][2], af[mi][3], ab + aoff[mi] + kk * 32);
#pragma unroll
            for (int g = 0; g < 4; g++)
                ldsm_x4(bf[2 * g][0], bf[2 * g][1], bf[2 * g + 1][0], bf[2 * g + 1][1],
                        bb + boff[g] + kk * 32);
#pragma unroll
            for (int mi = 0; mi < 2; mi++)
#pragma unroll
                for (int ni = 0; ni < 8; ni++)
                    mma_bf16(acc[mi][ni], af[mi], bf[ni]);
        }
        if (ks + 2 < NK) load_stage((ks + 2) % 3, (ks + 2) * 64);
        stg = (stg + 1) % 3;
    }

    float* Cb = g_S + (long)b * NC * NC;
    const int r = l >> 2, q = l & 3;
#pragma unroll
    for (int mi = 0; mi < 2; mi++)
#pragma unroll
    for (int ni = 0; ni < 8; ni++) {
        const int row = m0 + wm * 32 + mi * 16 + r;
        const int col = n0 + wn * 64 + ni * 8 + q * 2;
        *(float2*)&Cb[(long)row * NC + col]       = make_float2(acc[mi][ni][0], acc[mi][ni][1]);
        *(float2*)&Cb[(long)(row + 8) * NC + col] = make_float2(acc[mi][ni][2], acc[mi][ni][3]);
    }
}

// ---------------------------------------------------------------------------
// Stage 3: warp-per-row softmax (float4 vectorized), fp32 in -> bf16 out
// ---------------------------------------------------------------------------
__global__ __launch_bounds__(256) void k_softmax(const float* __restrict__ wq,
                                                 const float* __restrict__ wk) {
    const int row = blockIdx.x * 8 + (threadIdx.x >> 5);
    const int l = threadIdx.x & 31;
    const int c = row & (NC - 1);
    const float4* S4 = (const float4*)(g_S + (long)row * NC);
    const float4* W4 = (const float4*)wk;
    uint2* D2 = (uint2*)(g_Sh + (long)row * NC);
    const float sc = wq[c] * (1.0f / (float)NP);
    float4 v[4];
#pragma unroll
    for (int u = 0; u < 4; u++) {
        float4 s = S4[l + 32 * u];
        float4 k = W4[l + 32 * u];
        v[u] = make_float4(s.x * k.x * sc, s.y * k.y * sc, s.z * k.z * sc, s.w * k.w * sc);
    }
    float m = v[0].x;
#pragma unroll
    for (int u = 0; u < 4; u++)
        m = fmaxf(m, fmaxf(fmaxf(v[u].x, v[u].y), fmaxf(v[u].z, v[u].w)));
#pragma unroll
    for (int o = 16; o; o >>= 1) m = fmaxf(m, __shfl_xor_sync(0xffffffffu, m, o));
    float s = 0.f;
#pragma unroll
    for (int u = 0; u < 4; u++) {
        v[u].x = __expf(v[u].x - m); v[u].y = __expf(v[u].y - m);
        v[u].z = __expf(v[u].z - m); v[u].w = __expf(v[u].w - m);
        s += v[u].x + v[u].y + v[u].z + v[u].w;
    }
#pragma unroll
    for (int o = 16; o; o >>= 1) s += __shfl_xor_sync(0xffffffffu, s, o);
    const float inv = 1.0f / s;
#pragma unroll
    for (int u = 0; u < 4; u++)
        D2[l + 32 * u] = make_uint2(pack_bf2(v[u].x * inv, v[u].y * inv),
                                    pack_bf2(v[u].z * inv, v[u].w * inv));
}

// ---------------------------------------------------------------------------
// Stage 4: GEMM2 (NT) bf16: Fc[b,c,p] = sum_d Ac_h[b,c,d] * fsvT[p,d]
//   Fused epilogue: out = fq + lam*Fc ; rowmean & qsbar partials.
// ---------------------------------------------------------------------------
__global__ __launch_bounds__(256, 2) void k_gemm2(const float* __restrict__ fq,
                                                  const float* __restrict__ wsq,
                                                  const float* __restrict__ lamp,
                                                  float* __restrict__ out) {
    extern __shared__ __align__(16) __nv_bfloat16 smh[];
    const int b  = blockIdx.z;
    const int m0 = blockIdx.y * 128;
    const int n0 = blockIdx.x * 128;
    const __nv_bfloat16* A = g_Sh + (long)b * NC * NC;
    const __nv_bfloat16* B = g_fsvT;
    const int t = threadIdx.x;
    const int w = t >> 5, l = t & 31;
    const int wm = w & 3, wn = w >> 2;
    const int r = l >> 2, q = l & 3;

    unsigned aoff[2], boff[4];
#pragma unroll
    for (int mi = 0; mi < 2; mi++)
        aoff[mi] = ((wm * 32 + mi * 16 + (l & 15)) * BKH + (l >> 4) * 8) * 2;
#pragma unroll
    for (int g = 0; g < 4; g++)
        boff[g] = ((wn * 64 + g * 16 + ((l >> 4) << 3) + (l & 7)) * BKH + ((l >> 3) & 1) * 8) * 2;
    const unsigned smb = sptr(smh);

    float acc[2][8][4] = {};

    auto load_stage = [&](int stg, int k0) {
        __nv_bfloat16* as = smh + stg * STG_H;
        __nv_bfloat16* bs = as + THALF;
#pragma unroll
        for (int u = 0; u < 4; u++) {
            const int idx = u * 256 + t;
            const int row = idx >> 3, kc = (idx & 7) * 8;
            cpa16(as + row * BKH + kc, A + (long)(m0 + row) * NC + k0 + kc);
            cpa16(bs + row * BKH + kc, B + (long)(n0 + row) * NC + k0 + kc);
        }
        cpa_commit();
    };

    const int NK = NC / 64;   // 8
    load_stage(0, 0);
    load_stage(1, 64);

    int stg = 0;
    for (int ks = 0; ks < NK; ks++) {
        if (ks + 1 < NK) cpa_wait1(); else cpa_wait0();
        __syncthreads();
        const unsigned ab = smb + stg * (STG_H * 2);
        const unsigned bb = ab + THALF * 2;
#pragma unroll
        for (int kk = 0; kk < 4; kk++) {
            unsigned af[2][4], bf[8][2];
#pragma unroll
            for (int mi = 0; mi < 2; mi++)
                ldsm_x4(af[mi][0], af[mi][1], af[mi][2], af[mi][3], ab + aoff[mi] + kk * 32);
#pragma unroll
            for (int g = 0; g < 4; g++)
                ldsm_x4(bf[2 * g][0], bf[2 * g][1], bf[2 * g + 1][0], bf[2 * g + 1][1],
                        bb + boff[g] + kk * 32);
#pragma unroll
            for (int mi = 0; mi < 2; mi++)
#pragma unroll
                for (int ni = 0; ni < 8; ni++)
                    mma_bf16(acc[mi][ni], af[mi], bf[ni]);
        }
        if (ks + 2 < NK) load_stage((ks + 2) % 3, (ks + 2) * 64);
        stg = (stg + 1) % 3;
    }

    // ---- fused epilogue ----
    const float lam = *lamp;
    float rmloc[8][2] = {};
    float qbloc[2][2] = {};
#pragma unroll
    for (int mi = 0; mi < 2; mi++)
#pragma unroll
    for (int h = 0; h < 2; h++) {
        const int c = m0 + wm * 32 + mi * 16 + h * 8 + r;
        const float wc = wsq[c];
        const float wk2 = wc * g_ksbar[c];
        const float* fr = fq + (long)b * CP + (long)c * NP;
        float* orow = out + (long)b * CP + (long)c * NP;
        float qsum = 0.f;
#pragma unroll
        for (int ni = 0; ni < 8; ni++) {
            const int p = n0 + wn * 64 + ni * 8 + q * 2;
            const float v0 = acc[mi][ni][h * 2 + 0];
            const float v1 = acc[mi][ni][h * 2 + 1];
            const float2 f = *(const float2*)&fr[p];
            *(float2*)&orow[p] = make_float2(fmaf(lam, v0, f.x), fmaf(lam, v1, f.y));
            rmloc[ni][0] += v0 * wk2;
            rmloc[ni][1] += v1 * wk2;
            qsum += v0 + v1;
        }
        qbloc[mi][h] = qsum * wc;
    }
#pragma unroll
    for (int ni = 0; ni < 8; ni++)
#pragma unroll
    for (int j = 0; j < 2; j++) {
        float v = rmloc[ni][j];
        v += __shfl_xor_sync(0xffffffffu, v, 4);
        v += __shfl_xor_sync(0xffffffffu, v, 8);
        v += __shfl_xor_sync(0xffffffffu, v, 16);
        rmloc[ni][j] = v;
    }
#pragma unroll
    for (int mi = 0; mi < 2; mi++)
#pragma unroll
    for (int h = 0; h < 2; h++) {
        float v = qbloc[mi][h];
        v += __shfl_xor_sync(0xffffffffu, v, 1);
        v += __shfl_xor_sync(0xffffffffu, v, 2);
        qbloc[mi][h] = v;
    }
    __syncthreads();
    float* stage = (float*)smh;      // reuse smem
    float* rmstage = stage;          // [4][128]
    float* qbstage = stage + 512;    // [2][128]
    if (r == 0) {
#pragma unroll
        for (int ni = 0; ni < 8; ni++) {
            rmstage[wm * 128 + wn * 64 + ni * 8 + q * 2 + 0] = rmloc[ni][0];
            rmstage[wm * 128 + wn * 64 + ni * 8 + q * 2 + 1] = rmloc[ni][1];
        }
    }
    if (q == 0) {
#pragma unroll
        for (int mi = 0; mi < 2; mi++)
#pragma unroll
        for (int h = 0; h < 2; h++)
            qbstage[wn * 128 + wm * 32 + mi * 16 + h * 8 + r] = qbloc[mi][h];
    }
    __syncthreads();
    if (t < 128) {
        const float s = rmstage[t] + rmstage[128 + t] + rmstage[256 + t] + rmstage[384 + t];
        g_rm_part[(b * 4 + blockIdx.y) * NP + blockIdx.x * 128 + t] = s;
        const float s2 = qbstage[t] + qbstage[128 + t];
        g_qb_part[(b * 8 + blockIdx.x) * NC + blockIdx.y * 128 + t] = s2;
    }
}

// ---------------------------------------------------------------------------
// Stage 5: alpha[b,:] = softmax_p( rowmean[b,p] / (TAU*C) )
// ---------------------------------------------------------------------------
__global__ __launch_bounds__(256) void k_alpha(float* __restrict__ out_alpha) {
    const int b = blockIdx.x;
    const int t = threadIdx.x;
    float v[4];
#pragma unroll
    for (int u = 0; u < 4; u++) {
        const int p = t + u * 256;
        float s = 0.f;
#pragma unroll
        for (int mt = 0; mt < 4; mt++) s += g_rm_part[(b * 4 + mt) * NP + p];
        v[u] = s * (1.0f / 256.0f);
    }
    __shared__ float sh[33];
    float m = fmaxf(fmaxf(v[0], v[1]), fmaxf(v[2], v[3]));
#pragma unroll
    for (int o = 16; o; o >>= 1) m = fmaxf(m, __shfl_xor_sync(0xffffffffu, m, o));
    if ((t & 31) == 0) sh[t >> 5] = m;
    __syncthreads();
    if (t == 0) {
        float mm = sh[0];
#pragma unroll
        for (int i = 1; i < 8; i++) mm = fmaxf(mm, sh[i]);
        sh[32] = mm;
    }
    __syncthreads();
    m = sh[32];
    float s = 0.f;
#pragma unroll
    for (int u = 0; u < 4; u++) { v[u] = expf(v[u] - m); s += v[u]; }
#pragma unroll
    for (int o = 16; o; o >>= 1) s += __shfl_xor_sync(0xffffffffu, s, o);
    __syncthreads();
    if ((t & 31) == 0) sh[t >> 5] = s;
    __syncthreads();
    if (t == 0) {
        float ss = 0.f;
#pragma unroll
        for (int i = 0; i < 8; i++) ss += sh[i];
        sh[32] = ss;
    }
    __syncthreads();
    const float inv = 1.0f / sh[32];
#pragma unroll
    for (int u = 0; u < 4; u++) out_alpha[(long)b * NP + t + u * 256] = v[u] * inv;
}

// ---------------------------------------------------------------------------
// Stage 6a: beta logits, parallel GEMV.
//   grid (4 p-chunks, 16 b); block 256 threads, each owns one p.
//   logit[b,p] = (1/(TAU*C)) * sum_c qsbar[b,c]*wsk[c]*fsmean[c,p]
// ---------------------------------------------------------------------------
__global__ __launch_bounds__(256) void k_betamv(const float* __restrict__ wsk) {
    __shared__ float qsw[NC];
    const int b = blockIdx.y;
    const int p = blockIdx.x * 256 + threadIdx.x;
    const int t = threadIdx.x;
    for (int c = t; c < NC; c += 256) {
        float s = 0.f;
#pragma unroll
        for (int nt = 0; nt < 8; nt++) s += g_qb_part[(b * 8 + nt) * NC + c];
        qsw[c] = s * (1.0f / (float)NP) * wsk[c];
    }
    __syncthreads();
    float acc = 0.f;
#pragma unroll 8
    for (int c = 0; c < NC; c++)
        acc = fmaf(qsw[c], g_fsmean[(long)c * NP + p], acc);
    g_beta[(long)b * NP + p] = acc * (1.0f / 256.0f);   // 1/(TAU*C)
}

// ---------------------------------------------------------------------------
// Stage 6b: beta softmax over 1024 (in place), one block per b
// ---------------------------------------------------------------------------
__global__ __launch_bounds__(256) void k_betasm() {
    const int b = blockIdx.x;
    const int t = threadIdx.x;
    float* L = g_beta + (long)b * NP;
    float v[4];
#pragma unroll
    for (int u = 0; u < 4; u++) v[u] = L[t + u * 256];
    __shared__ float sh[33];
    float m = fmaxf(fmaxf(v[0], v[1]), fmaxf(v[2], v[3]));
#pragma unroll
    for (int o = 16; o; o >>= 1) m = fmaxf(m, __shfl_xor_sync(0xffffffffu, m, o));
    if ((t & 31) == 0) sh[t >> 5] = m;
    __syncthreads();
    if (t == 0) {
        float mm = sh[0];
#pragma unroll
        for (int i = 1; i < 8; i++) mm = fmaxf(mm, sh[i]);
        sh[32] = mm;
    }
    __syncthreads();
    m = sh[32];
    float s = 0.f;
#pragma unroll
    for (int u = 0; u < 4; u++) { v[u] = expf(v[u] - m); s += v[u]; }
#pragma unroll
    for (int o = 16; o; o >>= 1) s += __shfl_xor_sync(0xffffffffu, s, o);
    __syncthreads();
    if ((t & 31) == 0) sh[t >> 5] = s;
    __syncthreads();
    if (t == 0) {
        float ss = 0.f;
#pragma unroll
        for (int i = 0; i < 8; i++) ss += sh[i];
        sh[32] = ss;
    }
    __syncthreads();
    const float inv = 1.0f / sh[32];
#pragma unroll
    for (int u = 0; u < 4; u++) L[t + u * 256] = v[u] * inv;
}

// ---------------------------------------------------------------------------
// Stage 7: beta_mean broadcast
// ---------------------------------------------------------------------------
__global__ __launch_bounds__(256) void k_betamean(float* __restrict__ out_beta) {
    const int qi = blockIdx.x * 256 + threadIdx.x;
    float s = 0.f;
#pragma unroll
    for (int b = 0; b < NB; b++) s += g_beta[(long)b * NP + qi];
    s *= (1.0f / (float)NB);
#pragma unroll
    for (int rr = 0; rr < NB; rr++) out_beta[(long)rr * NP + qi] = s;
}

// ---------------------------------------------------------------------------
extern "C" void kernel_launch(void* const* d_in, const int* in_sizes, int n_in,
                              void* d_out, int out_size) {
    const float* f_q     = (const float*)d_in[0];
    const float* f_s     = (const float*)d_in[1];
    const float* w_cca_q = (const float*)d_in[2];
    const float* w_cca_k = (const float*)d_in[3];
    const float* w_cca_v = (const float*)d_in[4];
    const float* w_sca_q = (const float*)d_in[5];
    const float* w_sca_k = (const float*)d_in[6];
    const float* lam     = (const float*)d_in[7];
    float* out = (float*)d_out;

    cudaFuncSetAttribute(k_gemm1, cudaFuncAttributeMaxDynamicSharedMemorySize, GEMM_SMEM);
    cudaFuncSetAttribute(k_gemm2, cudaFuncAttributeMaxDynamicSharedMemorySize, GEMM_SMEM);

    k_prep<<<512, 256>>>(f_s, w_sca_k);
    k_trans<<<dim3(32, 16), 256>>>(w_cca_v);
    k_cvtq<<<8192, 256>>>(f_q);
    k_gemm1<<<dim3(4, 4, NB), 256, GEMM_SMEM>>>();
    k_softmax<<<1024, 256>>>(w_cca_q, w_cca_k);
    k_gemm2<<<dim3(8, 4, NB), 256, GEMM_SMEM>>>(f_q, w_sca_q, lam, out);
    k_alpha<<<NB, 256>>>(out + OUT_ALPHA);
    k_betamv<<<dim3(4, NB), 256>>>(w_sca_k);
    k_betasm<<<NB, 256>>>();
    k_betamean<<<4, 256>>>(out + OUT_BETA);
}

// round 7
// speedup vs baseline: 4.5048x; 1.1763x over previous
#include <cuda_runtime.h>
#include <cuda_bf16.h>
#include <math.h>

// Problem constants
static constexpr int NB = 16;           // B_Nq == B_Ns
static constexpr int NC = 512;          // C
static constexpr int NP = 1024;         // H*W
static constexpr long CP = (long)NC * NP;            // 524288
static constexpr long OUT_ALPHA = (long)NB * CP;     // 8388608
static constexpr long OUT_BETA  = OUT_ALPHA + (long)NB * NP;

// Scratch (device globals; allocation-free kernel_launch)
__device__ float          g_fsmean[NC * NP];          // mean_b f_s (fp32)
__device__ __nv_bfloat16  g_fsmean_h[NC * NP];        // bf16 [d,p] (GEMM1 B)
__device__ __nv_bfloat16  g_fsvT[NP * NC];            // bf16 [p,d] = wv[d]*fsmean[d,p]
__device__ __nv_bfloat16  g_Sh[(long)NB * NC * NC];   // softmaxed Ac (bf16)
__device__ float          g_ksbar[NC];
__device__ float          g_rm_part[NB * 4 * NP];
__device__ float          g_qb_part[NB * 8 * NC];
__device__ float          g_beta[NB * NP];            // beta logits -> beta

// ---------------------------------------------------------------------------
// PTX helpers
// ---------------------------------------------------------------------------
__device__ __forceinline__ unsigned sptr(const void* p) {
    return (unsigned)__cvta_generic_to_shared(p);
}
__device__ __forceinline__ void ldsm_x4(unsigned& r0, unsigned& r1, unsigned& r2, unsigned& r3,
                                        unsigned addr) {
    asm volatile("ldmatrix.sync.aligned.m8n8.x4.shared.b16 {%0,%1,%2,%3}, [%4];"
                 : "=r"(r0), "=r"(r1), "=r"(r2), "=r"(r3) : "r"(addr));
}
__device__ __forceinline__ void mma_bf16(float c[4], const unsigned a[4], const unsigned b[2]) {
    asm volatile(
        "mma.sync.aligned.m16n8k16.row.col.f32.bf16.bf16.f32 "
        "{%0,%1,%2,%3}, {%4,%5,%6,%7}, {%8,%9}, {%0,%1,%2,%3};"
        : "+f"(c[0]), "+f"(c[1]), "+f"(c[2]), "+f"(c[3])
        : "r"(a[0]), "r"(a[1]), "r"(a[2]), "r"(a[3]), "r"(b[0]), "r"(b[1]));
}
__device__ __forceinline__ void cpa16(const void* s, const void* g) {
    unsigned saddr = sptr(s);
    asm volatile("cp.async.cg.shared.global [%0], [%1], 16;" :: "r"(saddr), "l"(g));
}
__device__ __forceinline__ void cpa_commit() { asm volatile("cp.async.commit_group;"); }
__device__ __forceinline__ void cpa_wait2()  { asm volatile("cp.async.wait_group 2;"); }
__device__ __forceinline__ void cpa_wait1()  { asm volatile("cp.async.wait_group 1;"); }
__device__ __forceinline__ void cpa_wait0()  { asm volatile("cp.async.wait_group 0;"); }

__device__ __forceinline__ unsigned pack_bf2(float lo, float hi) {
    __nv_bfloat162 h = __floats2bfloat162_rn(lo, hi);
    return *(unsigned*)&h;
}

// ---------------------------------------------------------------------------
// Stage 1 (prep): block == one channel row c. fs_mean, bf16 copy, ksbar.
// ---------------------------------------------------------------------------
__global__ __launch_bounds__(256) void k_prep(const float* __restrict__ fs,
                                              const float* __restrict__ wsk) {
    const int c = blockIdx.x;
    const int t = threadIdx.x;
    const int i4 = c * 256 + t;
    const float4* f4 = (const float4*)fs;
    float4 a = make_float4(0.f, 0.f, 0.f, 0.f);
#pragma unroll
    for (int b = 0; b < NB; b++) {
        float4 v = f4[(long)b * (CP / 4) + i4];
        a.x += v.x; a.y += v.y; a.z += v.z; a.w += v.w;
    }
    const float s = 1.0f / (float)NB;
    a.x *= s; a.y *= s; a.z *= s; a.w *= s;
    ((float4*)g_fsmean)[i4] = a;
    ((uint2*)g_fsmean_h)[i4] = make_uint2(pack_bf2(a.x, a.y), pack_bf2(a.z, a.w));

    float rs = a.x + a.y + a.z + a.w;
    __shared__ float sh[8];
#pragma unroll
    for (int o = 16; o; o >>= 1) rs += __shfl_xor_sync(0xffffffffu, rs, o);
    if ((t & 31) == 0) sh[t >> 5] = rs;
    __syncthreads();
    if (t == 0) {
        float tot = 0.f;
#pragma unroll
        for (int i = 0; i < 8; i++) tot += sh[i];
        g_ksbar[c] = wsk[c] * tot * (1.0f / (float)NP);
    }
}

// ---------------------------------------------------------------------------
// Stage 1c: fsvT[p,d] = wv[d]*fsmean[d,p]  (bf16, K-major for GEMM2 B)
// ---------------------------------------------------------------------------
__global__ __launch_bounds__(256) void k_trans(const float* __restrict__ wv) {
    __shared__ float tile[32][33];
    const int p0 = blockIdx.x * 32, d0 = blockIdx.y * 32;
    const int tx = threadIdx.x & 31, ty = threadIdx.x >> 5;   // ty 0..7
#pragma unroll
    for (int r = 0; r < 4; r++) {
        const int d = d0 + ty + r * 8;
        tile[ty + r * 8][tx] = g_fsmean[(long)d * NP + p0 + tx] * wv[d];
    }
    __syncthreads();
#pragma unroll
    for (int r = 0; r < 4; r++) {
        const int p = p0 + ty + r * 8;
        g_fsvT[(long)p * NC + d0 + tx] = __float2bfloat16_rn(tile[tx][ty + r * 8]);
    }
}

// ---------------------------------------------------------------------------
// Stage 2: FUSED GEMM1 + row softmax.
//   CTA tile 64(c) x 512(d), 512 threads (16 warps: wm=w&1, wn=w>>1).
//   S[b,c,d] = sum_p fq[b,c,p]*fsmean_h[d,p]; Ac = softmax_d(S*wq[c]*wk[d]/P)
//   A: fp32 f_q loaded directly (reg-staged -> bf16 smem). B: 3-stage cp.async.
// ---------------------------------------------------------------------------
static constexpr int G1_BKH = 40;                       // padded halves per row
static constexpr int G1_AH = 64 * G1_BKH;               // 2560 halves / A stage
static constexpr int G1_BH = 512 * G1_BKH;              // 20480 halves / B stage
static constexpr int G1_STG_H = G1_AH + G1_BH;          // 23040
static constexpr int G1_SMEM = 3 * G1_STG_H * 2 + 4096; // + softmax red buffers

__global__ __launch_bounds__(512, 1) void k_gemm1f(const float* __restrict__ fq,
                                                   const float* __restrict__ wq,
                                                   const float* __restrict__ wk) {
    extern __shared__ __align__(16) __nv_bfloat16 smh[];
    const int b  = blockIdx.y;
    const int m0 = blockIdx.x * 64;
    const float* A = fq + (long)b * CP + (long)m0 * NP;
    const __nv_bfloat16* B = g_fsmean_h;
    const int t = threadIdx.x;
    const int w = t >> 5, l = t & 31;
    const int wm = w & 1, wn = w >> 1;     // 2 x 8 warp grid
    const int r = l >> 2, q = l & 3;

    unsigned aoff[2], boff[4];
#pragma unroll
    for (int mi = 0; mi < 2; mi++)
        aoff[mi] = ((wm * 32 + mi * 16 + (l & 15)) * G1_BKH + (l >> 4) * 8) * 2;
#pragma unroll
    for (int g = 0; g < 4; g++)
        boff[g] = ((wn * 64 + g * 16 + ((l >> 4) << 3) + (l & 7)) * G1_BKH + ((l >> 3) & 1) * 8) * 2;
    const unsigned smb = sptr(smh);

    // A loader mapping: 1 float4 per thread per stage (64 rows x 32 k fp32)
    const int arow = t >> 3, akc = (t & 7) * 4;
    // B loader: 4 chunks per thread per stage (512 rows x 32 halves)
    float acc[2][8][4] = {};

    auto ldA = [&](int k0) -> float4 {
        return *(const float4*)(A + (long)arow * NP + k0 + akc);
    };
    auto stA = [&](int stg, float4 v) {
        *(uint2*)((char*)(smh + stg * G1_STG_H) + (arow * G1_BKH + akc) * 2) =
            make_uint2(pack_bf2(v.x, v.y), pack_bf2(v.z, v.w));
    };
    auto ldB = [&](int stg, int k0) {
        __nv_bfloat16* bs = smh + stg * G1_STG_H + G1_AH;
#pragma unroll
        for (int u = 0; u < 4; u++) {
            const int idx = u * 512 + t;
            const int row = idx >> 2, kc = (idx & 3) * 8;
            cpa16(bs + row * G1_BKH + kc, B + (long)row * NP + k0 + kc);
        }
        cpa_commit();
    };

    const int NK = NP / 32;   // 32
    float4 a0 = ldA(0);
    ldB(0, 0);
    float4 a1 = ldA(32);
    ldB(1, 32);
    stA(0, a0);
    stA(1, a1);
    float4 ar = ldA(64);
    ldB(2, 64);

    for (int ks = 0; ks < NK; ks++) {
        const int rem = NK - 1 - ks;
        if (rem >= 2) cpa_wait2(); else if (rem == 1) cpa_wait1(); else cpa_wait0();
        __syncthreads();
        if (ks + 2 < NK) stA((ks + 2) % 3, ar);
        const int stg = ks % 3;
        const unsigned ab = smb + stg * (G1_STG_H * 2);
        const unsigned bb = ab + G1_AH * 2;
#pragma unroll
        for (int kk = 0; kk < 2; kk++) {
            unsigned af[2][4], bf[8][2];
#pragma unroll
            for (int mi = 0; mi < 2; mi++)
                ldsm_x4(af[mi][0], af[mi][1], af[mi][2], af[mi][3], ab + aoff[mi] + kk * 32);
#pragma unroll
            for (int g = 0; g < 4; g++)
                ldsm_x4(bf[2 * g][0], bf[2 * g][1], bf[2 * g + 1][0], bf[2 * g + 1][1],
                        bb + boff[g] + kk * 32);
#pragma unroll
            for (int mi = 0; mi < 2; mi++)
#pragma unroll
                for (int ni = 0; ni < 8; ni++)
                    mma_bf16(acc[mi][ni], af[mi], bf[ni]);
        }
        if (ks + 3 < NK) ar = ldA((ks + 3) * 32);
        if (ks + 2 < NK) ldB((ks + 2) % 3, (ks + 2) * 32);
    }

    // ---- fused softmax epilogue ----
    float* red  = (float*)(smh + 3 * G1_STG_H);   // [64][8]
    float* red2 = red + 512;                      // [64][8]
    float rw[2][2], cw[8][2];
#pragma unroll
    for (int mi = 0; mi < 2; mi++)
#pragma unroll
    for (int h = 0; h < 2; h++)
        rw[mi][h] = wq[m0 + wm * 32 + mi * 16 + h * 8 + r] * (1.0f / (float)NP);
#pragma unroll
    for (int ni = 0; ni < 8; ni++) {
        cw[ni][0] = wk[wn * 64 + ni * 8 + q * 2 + 0];
        cw[ni][1] = wk[wn * 64 + ni * 8 + q * 2 + 1];
    }
#pragma unroll
    for (int mi = 0; mi < 2; mi++)
#pragma unroll
    for (int ni = 0; ni < 8; ni++)
#pragma unroll
    for (int h = 0; h < 2; h++) {
        acc[mi][ni][h * 2 + 0] *= rw[mi][h] * cw[ni][0];
        acc[mi][ni][h * 2 + 1] *= rw[mi][h] * cw[ni][1];
    }
    // row max: per-thread over 16 vals, reduce over q lanes, then cross-warp
#pragma unroll
    for (int mi = 0; mi < 2; mi++)
#pragma unroll
    for (int h = 0; h < 2; h++) {
        float m = acc[mi][0][h * 2];
#pragma unroll
        for (int ni = 0; ni < 8; ni++)
            m = fmaxf(m, fmaxf(acc[mi][ni][h * 2], acc[mi][ni][h * 2 + 1]));
        m = fmaxf(m, __shfl_xor_sync(0xffffffffu, m, 1));
        m = fmaxf(m, __shfl_xor_sync(0xffffffffu, m, 2));
        if (q == 0) red[(wm * 32 + mi * 16 + h * 8 + r) * 8 + wn] = m;
    }
    __syncthreads();
    float rmax[2][2];
#pragma unroll
    for (int mi = 0; mi < 2; mi++)
#pragma unroll
    for (int h = 0; h < 2; h++) {
        const float* rr = red + (wm * 32 + mi * 16 + h * 8 + r) * 8;
        float m = rr[0];
#pragma unroll
        for (int i = 1; i < 8; i++) m = fmaxf(m, rr[i]);
        rmax[mi][h] = m;
    }
    // exp + row sum
#pragma unroll
    for (int mi = 0; mi < 2; mi++)
#pragma unroll
    for (int h = 0; h < 2; h++) {
        float s = 0.f;
#pragma unroll
        for (int ni = 0; ni < 8; ni++) {
            float e0 = __expf(acc[mi][ni][h * 2 + 0] - rmax[mi][h]);
            float e1 = __expf(acc[mi][ni][h * 2 + 1] - rmax[mi][h]);
            acc[mi][ni][h * 2 + 0] = e0;
            acc[mi][ni][h * 2 + 1] = e1;
            s += e0 + e1;
        }
        s += __shfl_xor_sync(0xffffffffu, s, 1);
        s += __shfl_xor_sync(0xffffffffu, s, 2);
        if (q == 0) red2[(wm * 32 + mi * 16 + h * 8 + r) * 8 + wn] = s;
    }
    __syncthreads();
    __nv_bfloat16* D = g_Sh + (long)b * NC * NC;
#pragma unroll
    for (int mi = 0; mi < 2; mi++)
#pragma unroll
    for (int h = 0; h < 2; h++) {
        const int c = m0 + wm * 32 + mi * 16 + h * 8 + r;
        const float* rr = red2 + (c - m0) * 8;
        float s = 0.f;
#pragma unroll
        for (int i = 0; i < 8; i++) s += rr[i];
        const float inv = 1.0f / s;
#pragma unroll
        for (int ni = 0; ni < 8; ni++)
            *(unsigned*)&D[(long)c * NC + wn * 64 + ni * 8 + q * 2] =
                pack_bf2(acc[mi][ni][h * 2] * inv, acc[mi][ni][h * 2 + 1] * inv);
    }
}

// ---------------------------------------------------------------------------
// GEMM2 tiles: 128x128 CTA, BK=64, 3-stage cp.async. BKH=72 padding.
// ---------------------------------------------------------------------------
static constexpr int BKH = 72;
static constexpr int THALF = 128 * BKH;
static constexpr int STG_H = 2 * THALF;
static constexpr int GEMM_SMEM = 3 * STG_H * 2;   // 110592 bytes

__global__ __launch_bounds__(256, 2) void k_gemm2(const float* __restrict__ fq,
                                                  const float* __restrict__ wsq,
                                                  const float* __restrict__ lamp,
                                                  float* __restrict__ out) {
    extern __shared__ __align__(16) __nv_bfloat16 smh[];
    const int b  = blockIdx.z;
    const int m0 = blockIdx.y * 128;
    const int n0 = blockIdx.x * 128;
    const __nv_bfloat16* A = g_Sh + (long)b * NC * NC;
    const __nv_bfloat16* B = g_fsvT;
    const int t = threadIdx.x;
    const int w = t >> 5, l = t & 31;
    const int wm = w & 3, wn = w >> 2;
    const int r = l >> 2, q = l & 3;

    unsigned aoff[2], boff[4];
#pragma unroll
    for (int mi = 0; mi < 2; mi++)
        aoff[mi] = ((wm * 32 + mi * 16 + (l & 15)) * BKH + (l >> 4) * 8) * 2;
#pragma unroll
    for (int g = 0; g < 4; g++)
        boff[g] = ((wn * 64 + g * 16 + ((l >> 4) << 3) + (l & 7)) * BKH + ((l >> 3) & 1) * 8) * 2;
    const unsigned smb = sptr(smh);

    float acc[2][8][4] = {};

    auto load_stage = [&](int stg, int k0) {
        __nv_bfloat16* as = smh + stg * STG_H;
        __nv_bfloat16* bs = as + THALF;
#pragma unroll
        for (int u = 0; u < 4; u++) {
            const int idx = u * 256 + t;
            const int row = idx >> 3, kc = (idx & 7) * 8;
            cpa16(as + row * BKH + kc, A + (long)(m0 + row) * NC + k0 + kc);
            cpa16(bs + row * BKH + kc, B + (long)(n0 + row) * NC + k0 + kc);
        }
        cpa_commit();
    };

    const int NK = NC / 64;   // 8
    load_stage(0, 0);
    load_stage(1, 64);

    int stg = 0;
    for (int ks = 0; ks < NK; ks++) {
        if (ks + 1 < NK) cpa_wait1(); else cpa_wait0();
        __syncthreads();
        const unsigned ab = smb + stg * (STG_H * 2);
        const unsigned bb = ab + THALF * 2;
#pragma unroll
        for (int kk = 0; kk < 4; kk++) {
            unsigned af[2][4], bf[8][2];
#pragma unroll
            for (int mi = 0; mi < 2; mi++)
                ldsm_x4(af[mi][0], af[mi][1], af[mi][2], af[mi][3], ab + aoff[mi] + kk * 32);
#pragma unroll
            for (int g = 0; g < 4; g++)
                ldsm_x4(bf[2 * g][0], bf[2 * g][1], bf[2 * g + 1][0], bf[2 * g + 1][1],
                        bb + boff[g] + kk * 32);
#pragma unroll
            for (int mi = 0; mi < 2; mi++)
#pragma unroll
                for (int ni = 0; ni < 8; ni++)
                    mma_bf16(acc[mi][ni], af[mi], bf[ni]);
        }
        if (ks + 2 < NK) load_stage((ks + 2) % 3, (ks + 2) * 64);
        stg = (stg + 1) % 3;
    }

    // ---- fused epilogue ----
    const float lam = *lamp;
    float rmloc[8][2] = {};
    float qbloc[2][2] = {};
#pragma unroll
    for (int mi = 0; mi < 2; mi++)
#pragma unroll
    for (int h = 0; h < 2; h++) {
        const int c = m0 + wm * 32 + mi * 16 + h * 8 + r;
        const float wc = wsq[c];
        const float wk2 = wc * g_ksbar[c];
        const float* fr = fq + (long)b * CP + (long)c * NP;
        float* orow = out + (long)b * CP + (long)c * NP;
        float qsum = 0.f;
#pragma unroll
        for (int ni = 0; ni < 8; ni++) {
            const int p = n0 + wn * 64 + ni * 8 + q * 2;
            const float v0 = acc[mi][ni][h * 2 + 0];
            const float v1 = acc[mi][ni][h * 2 + 1];
            const float2 f = *(const float2*)&fr[p];
            *(float2*)&orow[p] = make_float2(fmaf(lam, v0, f.x), fmaf(lam, v1, f.y));
            rmloc[ni][0] += v0 * wk2;
            rmloc[ni][1] += v1 * wk2;
            qsum += v0 + v1;
        }
        qbloc[mi][h] = qsum * wc;
    }
#pragma unroll
    for (int ni = 0; ni < 8; ni++)
#pragma unroll
    for (int j = 0; j < 2; j++) {
        float v = rmloc[ni][j];
        v += __shfl_xor_sync(0xffffffffu, v, 4);
        v += __shfl_xor_sync(0xffffffffu, v, 8);
        v += __shfl_xor_sync(0xffffffffu, v, 16);
        rmloc[ni][j] = v;
    }
#pragma unroll
    for (int mi = 0; mi < 2; mi++)
#pragma unroll
    for (int h = 0; h < 2; h++) {
        float v = qbloc[mi][h];
        v += __shfl_xor_sync(0xffffffffu, v, 1);
        v += __shfl_xor_sync(0xffffffffu, v, 2);
        qbloc[mi][h] = v;
    }
    __syncthreads();
    float* stage = (float*)smh;      // reuse smem
    float* rmstage = stage;          // [4][128]
    float* qbstage = stage + 512;    // [2][128]
    if (r == 0) {
#pragma unroll
        for (int ni = 0; ni < 8; ni++) {
            rmstage[wm * 128 + wn * 64 + ni * 8 + q * 2 + 0] = rmloc[ni][0];
            rmstage[wm * 128 + wn * 64 + ni * 8 + q * 2 + 1] = rmloc[ni][1];
        }
    }
    if (q == 0) {
#pragma unroll
        for (int mi = 0; mi < 2; mi++)
#pragma unroll
        for (int h = 0; h < 2; h++)
            qbstage[wn * 128 + wm * 32 + mi * 16 + h * 8 + r] = qbloc[mi][h];
    }
    __syncthreads();
    if (t < 128) {
        const float s = rmstage[t] + rmstage[128 + t] + rmstage[256 + t] + rmstage[384 + t];
        g_rm_part[(b * 4 + blockIdx.y) * NP + blockIdx.x * 128 + t] = s;
        const float s2 = qbstage[t] + qbstage[128 + t];
        g_qb_part[(b * 8 + blockIdx.x) * NC + blockIdx.y * 128 + t] = s2;
    }
}

// ---------------------------------------------------------------------------
// Stage 5: alpha[b,:] = softmax_p( rowmean[b,p] / (TAU*C) )
// ---------------------------------------------------------------------------
__global__ __launch_bounds__(256) void k_alpha(float* __restrict__ out_alpha) {
    const int b = blockIdx.x;
    const int t = threadIdx.x;
    float v[4];
#pragma unroll
    for (int u = 0; u < 4; u++) {
        const int p = t + u * 256;
        float s = 0.f;
#pragma unroll
        for (int mt = 0; mt < 4; mt++) s += g_rm_part[(b * 4 + mt) * NP + p];
        v[u] = s * (1.0f / 256.0f);
    }
    __shared__ float sh[33];
    float m = fmaxf(fmaxf(v[0], v[1]), fmaxf(v[2], v[3]));
#pragma unroll
    for (int o = 16; o; o >>= 1) m = fmaxf(m, __shfl_xor_sync(0xffffffffu, m, o));
    if ((t & 31) == 0) sh[t >> 5] = m;
    __syncthreads();
    if (t == 0) {
        float mm = sh[0];
#pragma unroll
        for (int i = 1; i < 8; i++) mm = fmaxf(mm, sh[i]);
        sh[32] = mm;
    }
    __syncthreads();
    m = sh[32];
    float s = 0.f;
#pragma unroll
    for (int u = 0; u < 4; u++) { v[u] = expf(v[u] - m); s += v[u]; }
#pragma unroll
    for (int o = 16; o; o >>= 1) s += __shfl_xor_sync(0xffffffffu, s, o);
    __syncthreads();
    if ((t & 31) == 0) sh[t >> 5] = s;
    __syncthreads();
    if (t == 0) {
        float ss = 0.f;
#pragma unroll
        for (int i = 0; i < 8; i++) ss += sh[i];
        sh[32] = ss;
    }
    __syncthreads();
    const float inv = 1.0f / sh[32];
#pragma unroll
    for (int u = 0; u < 4; u++) out_alpha[(long)b * NP + t + u * 256] = v[u] * inv;
}

// ---------------------------------------------------------------------------
// Stage 6a: beta logits, parallel GEMV. grid (4 p-chunks, 16 b).
// ---------------------------------------------------------------------------
__global__ __launch_bounds__(256) void k_betamv(const float* __restrict__ wsk) {
    __shared__ float qsw[NC];
    const int b = blockIdx.y;
    const int p = blockIdx.x * 256 + threadIdx.x;
    const int t = threadIdx.x;
    for (int c = t; c < NC; c += 256) {
        float s = 0.f;
#pragma unroll
        for (int nt = 0; nt < 8; nt++) s += g_qb_part[(b * 8 + nt) * NC + c];
        qsw[c] = s * (1.0f / (float)NP) * wsk[c];
    }
    __syncthreads();
    float acc = 0.f;
#pragma unroll 8
    for (int c = 0; c < NC; c++)
        acc = fmaf(qsw[c], g_fsmean[(long)c * NP + p], acc);
    g_beta[(long)b * NP + p] = acc * (1.0f / 256.0f);   // 1/(TAU*C)
}

// ---------------------------------------------------------------------------
// Stage 6b: beta softmax over 1024 (in place), one block per b
// ---------------------------------------------------------------------------
__global__ __launch_bounds__(256) void k_betasm() {
    const int b = blockIdx.x;
    const int t = threadIdx.x;
    float* L = g_beta + (long)b * NP;
    float v[4];
#pragma unroll
    for (int u = 0; u < 4; u++) v[u] = L[t + u * 256];
    __shared__ float sh[33];
    float m = fmaxf(fmaxf(v[0], v[1]), fmaxf(v[2], v[3]));
#pragma unroll
    for (int o = 16; o; o >>= 1) m = fmaxf(m, __shfl_xor_sync(0xffffffffu, m, o));
    if ((t & 31) == 0) sh[t >> 5] = m;
    __syncthreads();
    if (t == 0) {
        float mm = sh[0];
#pragma unroll
        for (int i = 1; i < 8; i++) mm = fmaxf(mm, sh[i]);
        sh[32] = mm;
    }
    __syncthreads();
    m = sh[32];
    float s = 0.f;
#pragma unroll
    for (int u = 0; u < 4; u++) { v[u] = expf(v[u] - m); s += v[u]; }
#pragma unroll
    for (int o = 16; o; o >>= 1) s += __shfl_xor_sync(0xffffffffu, s, o);
    __syncthreads();
    if ((t & 31) == 0) sh[t >> 5] = s;
    __syncthreads();
    if (t == 0) {
        float ss = 0.f;
#pragma unroll
        for (int i = 0; i < 8; i++) ss += sh[i];
        sh[32] = ss;
    }
    __syncthreads();
    const float inv = 1.0f / sh[32];
#pragma unroll
    for (int u = 0; u < 4; u++) L[t + u * 256] = v[u] * inv;
}

// ---------------------------------------------------------------------------
// Stage 7: beta_mean broadcast
// ---------------------------------------------------------------------------
__global__ __launch_bounds__(256) void k_betamean(float* __restrict__ out_beta) {
    const int qi = blockIdx.x * 256 + threadIdx.x;
    float s = 0.f;
#pragma unroll
    for (int b = 0; b < NB; b++) s += g_beta[(long)b * NP + qi];
    s *= (1.0f / (float)NB);
#pragma unroll
    for (int rr = 0; rr < NB; rr++) out_beta[(long)rr * NP + qi] = s;
}

// ---------------------------------------------------------------------------
extern "C" void kernel_launch(void* const* d_in, const int* in_sizes, int n_in,
                              void* d_out, int out_size) {
    const float* f_q     = (const float*)d_in[0];
    const float* f_s     = (const float*)d_in[1];
    const float* w_cca_q = (const float*)d_in[2];
    const float* w_cca_k = (const float*)d_in[3];
    const float* w_cca_v = (const float*)d_in[4];
    const float* w_sca_q = (const float*)d_in[5];
    const float* w_sca_k = (const float*)d_in[6];
    const float* lam     = (const float*)d_in[7];
    float* out = (float*)d_out;

    cudaFuncSetAttribute(k_gemm1f, cudaFuncAttributeMaxDynamicSharedMemorySize, G1_SMEM);
    cudaFuncSetAttribute(k_gemm2, cudaFuncAttributeMaxDynamicSharedMemorySize, GEMM_SMEM);

    k_prep<<<512, 256>>>(f_s, w_sca_k);
    k_trans<<<dim3(32, 16), 256>>>(w_cca_v);
    k_gemm1f<<<dim3(8, NB), 512, G1_SMEM>>>(f_q, w_cca_q, w_cca_k);
    k_gemm2<<<dim3(8, 4, NB), 256, GEMM_SMEM>>>(f_q, w_sca_q, lam, out);
    k_alpha<<<NB, 256>>>(out + OUT_ALPHA);
    k_betamv<<<dim3(4, NB), 256>>>(w_sca_k);
    k_betasm<<<NB, 256>>>();
    k_betamean<<<4, 256>>>(out + OUT_BETA);
}